// round 11
// baseline (speedup 1.0000x reference)
#include <cuda_runtime.h>
#include <cuda_bf16.h>
#include <math.h>
#include <string.h>

#define BN 32
#define TIN 256
#define TOUT 400
#define EDIM 512
#define ADIM 128
#define NFLT 32
#define KSZ 31
#define PRE 256
#define DDIM 1024
#define NMEL 80
#define ZN 4096
#define NCTA 128
#define NTHR 512
#define CHUNKK 256
#define KST0 112
#define KST1 160

// dynamic smem layout
#define OFF_BB 0              // 3 * 32768 B buffers
#define OFF_XH 98304          // 2 * 16384 A-hi (fragment order)
#define OFF_XL 131072         // 2 * 16384 A-lo
#define OFF_ZF 163840         // 4096
#define OFF_KEYS 167936       // 32 * 256 * 4 persistent keys slice
#define DSMEM_BYTES 200704

// ---------------- persistent device scratch ----------------
__device__ float g_prenet[TOUT * BN * PRE];
__device__ float g_keysT[BN * ADIM * TIN];
__device__ float g_maskneg[BN * TIN];
__device__ float g_h0[2][BN * DDIM];
__device__ float g_h1[2][BN * DDIM];
__device__ float g_ctx[BN * EDIM];
__device__ float g_wcum[BN * TIN];
__device__ float g_epart[4 * BN * TIN];
__device__ float g_h1all[TOUT * BN * DDIM];
__device__ float g_ctxall[TOUT * BN * EDIM];
// contention-free barrier flags: one 128B-strided word per CTA
__device__ unsigned g_flags[NCTA * 32];
__device__ unsigned g_relv[NCTA * 32];
__device__ uint4 g_pb0[(size_t)NCTA * KST0 * 4 * 32];
__device__ uint4 g_pb1[(size_t)NCTA * KST1 * 4 * 32];

__device__ __forceinline__ float sigmoidf_(float x) { return 1.f / (1.f + expf(-x)); }

__device__ __forceinline__ unsigned smem_u32(const void* p) {
    unsigned a;
    asm("{ .reg .u64 t; cvta.to.shared.u64 t, %1; cvt.u32.u64 %0, t; }"
        : "=r"(a) : "l"(p));
    return a;
}
__device__ __forceinline__ void cpasync16(unsigned dst, const void* src) {
    asm volatile("cp.async.cg.shared.global [%0], [%1], 16;" :: "r"(dst), "l"(src));
}
#define CP_COMMIT() asm volatile("cp.async.commit_group;" ::: "memory")
#define CP_WAITG(n) asm volatile("cp.async.wait_group %0;" :: "n"(n) : "memory")

__device__ __forceinline__ unsigned pk2(__nv_bfloat16 a, __nv_bfloat16 b) {
    __nv_bfloat162 t(a, b);
    unsigned r;
    memcpy(&r, &t, 4);
    return r;
}
__device__ __forceinline__ void mma16816(float* d, unsigned a0, unsigned a1,
                                         unsigned a2, unsigned a3,
                                         unsigned b0, unsigned b1) {
    asm volatile("mma.sync.aligned.m16n8k16.row.col.f32.bf16.bf16.f32 "
                 "{%0,%1,%2,%3}, {%4,%5,%6,%7}, {%8,%9}, {%0,%1,%2,%3};"
                 : "+f"(d[0]), "+f"(d[1]), "+f"(d[2]), "+f"(d[3])
                 : "r"(a0), "r"(a1), "r"(a2), "r"(a3), "r"(b0), "r"(b1));
}

// ---------------- contention-free grid barrier ----------------
// Each CTA owns a private arrival word and a private release word (128B apart).
// CTA 0's first 128 threads poll arrival flags in parallel, then fan out the
// release to 128 private words. No same-address polling anywhere.
__device__ __forceinline__ void grid_bar(unsigned gen, int j, int tid) {
    __syncthreads();
    if (j == 0) {
        if (tid >= 1 && tid < NCTA) {
            unsigned v;
            do {
                asm volatile("ld.acquire.gpu.u32 %0, [%1];"
                             : "=r"(v) : "l"(&g_flags[tid * 32]));
            } while (v != gen);
        }
        __syncthreads();
        if (tid == 0) asm volatile("fence.acq_rel.gpu;" ::: "memory");
        __syncthreads();
        if (tid < NCTA)
            asm volatile("st.release.gpu.u32 [%0], %1;"
                         :: "l"(&g_relv[tid * 32]), "r"(gen) : "memory");
    } else {
        if (tid == 0) {
            asm volatile("fence.acq_rel.gpu;" ::: "memory");
            asm volatile("st.release.gpu.u32 [%0], %1;"
                         :: "l"(&g_flags[j * 32]), "r"(gen) : "memory");
            unsigned v;
            do {
                asm volatile("ld.acquire.gpu.u32 %0, [%1];"
                             : "=r"(v) : "l"(&g_relv[j * 32]));
            } while (v != gen);
        }
        __syncthreads();
    }
}

// ---------------- attention smem structs (alias GEMM region) ------------
struct AttC {
    float h1s[DDIM];
    float wp[TIN + KSZ];
    float cws[KSZ * NFLT];
    float cbs[NFLT];
    float ldws[NFLT * 32];
    float ldbs[32], vws[32];
    float qred[16][32];
    float qp[32];
    float es[2][TIN];
    float loc[TIN][NFLT + 1];
};
struct AttD { float red[256]; float ws[256]; float cred[4][128]; };

// ---------------- combined weight pack ----------------
__device__ void pack_tile(const float* __restrict__ wK, const float* __restrict__ wR,
                          int KST, int KB1, uint4* __restrict__ out,
                          int ks, int nb, float (*w)[128]) {
    int k0 = ks * 16;
    const float* W = (k0 < KB1) ? wK + (size_t)k0 * ZN : wR + (size_t)(k0 - KB1) * ZN;
    int N0 = nb * 128;
    for (int i = threadIdx.x; i < 2048; i += 256)
        w[i >> 7][i & 127] = W[(size_t)(i >> 7) * ZN + N0 + (i & 127)];
    __syncthreads();
    int g = N0 >> 10, jbase = (N0 & 1023) >> 3;
    for (int s = threadIdx.x; s < 512; s += 256) {
        int jl = s >> 5, lane = s & 31;
        int q = lane & 3, t4 = lane >> 2;
        int n = jl * 8 + t4;
        float v0 = w[2 * q][n], v1 = w[2 * q + 1][n];
        float v2 = w[2 * q + 8][n], v3 = w[2 * q + 9][n];
        __nv_bfloat16 h0 = __float2bfloat16_rn(v0), h1 = __float2bfloat16_rn(v1);
        __nv_bfloat16 h2 = __float2bfloat16_rn(v2), h3 = __float2bfloat16_rn(v3);
        unsigned bh0 = pk2(h0, h1), bh1 = pk2(h2, h3);
        unsigned bl0 = pk2(__float2bfloat16_rn(v0 - __bfloat162float(h0)),
                           __float2bfloat16_rn(v1 - __bfloat162float(h1)));
        unsigned bl1 = pk2(__float2bfloat16_rn(v2 - __bfloat162float(h2)),
                           __float2bfloat16_rn(v3 - __bfloat162float(h3)));
        int jj = jbase + jl;
        out[((size_t)(jj * KST + ks) * 4 + g) * 32 + lane] = make_uint4(bh0, bh1, bl0, bl1);
    }
}

__global__ void pack_all_kernel(const float* __restrict__ l0k, const float* __restrict__ l0r,
                                const float* __restrict__ l1k, const float* __restrict__ l1r,
                                uint4* __restrict__ o0, uint4* __restrict__ o1) {
    __shared__ float w[16][128];
    int bid = blockIdx.x;
    if (bid < KST0 * 32)
        pack_tile(l0k, l0r, KST0, 768, o0, bid % KST0, bid / KST0, w);
    else {
        bid -= KST0 * 32;
        pack_tile(l1k, l1r, KST1, 1536, o1, bid % KST1, bid / KST1, w);
    }
}

// ---------------- bf16 MMA GEMM (unchanged from R10) ----------
template <int KTOT, int KB0, int KB1, int SA>
__device__ __forceinline__ void gemm_mma(char* dsm, int j,
                                         const float* __restrict__ xA,
                                         const float* __restrict__ xB,
                                         const float* __restrict__ xC,
                                         const uint4* __restrict__ pB,
                                         float* __restrict__ zf) {
    constexpr int NC = KTOT / CHUNKK;
    constexpr int KST = KTOT / 16;
    const int tid = threadIdx.x;
    uint4* Bb = (uint4*)(dsm + OFF_BB);
    unsigned* xhU = (unsigned*)(dsm + OFF_XH);
    unsigned* xlU = (unsigned*)(dsm + OFF_XL);

    if (tid >= 256) {
        const int p = tid - 256;
        const int row = p >> 3, kseg = p & 7;
        const int mi = row >> 4, rloc = row & 15, t4 = rloc & 7, rbit = rloc >> 3;
        float4 xr[8];
        auto ldgx = [&](int c) {
            int k0 = c * CHUNKK + kseg * 32;
            const float* s;
            if (k0 < KB0)      s = xA + row * SA + k0;
            else if (k0 < KB1) s = xB + row * EDIM + (k0 - KB0);
            else               s = xC + row * DDIM + (k0 - KB1);
            #pragma unroll
            for (int i = 0; i < 8; i++) xr[i] = __ldcg((const float4*)s + i);
        };
        auto stsx = [&](int c) {
            int boff = (c & 1) * 4096;
            float f[32];
            #pragma unroll
            for (int i = 0; i < 8; i++) {
                f[4 * i] = xr[i].x;     f[4 * i + 1] = xr[i].y;
                f[4 * i + 2] = xr[i].z; f[4 * i + 3] = xr[i].w;
            }
            #pragma unroll
            for (int u = 0; u < 16; u++) {
                int k2 = kseg * 16 + u;
                int ksg = k2 >> 3, p8 = k2 & 7;
                int q = p8 & 3, kh = p8 >> 2;
                int idx = boff + (((mi * 16 + ksg) * 32) + t4 * 4 + q) * 4 +
                          (rbit | (kh << 1));
                float a = f[2 * u], b = f[2 * u + 1];
                __nv_bfloat16 ha = __float2bfloat16_rn(a), hb = __float2bfloat16_rn(b);
                xhU[idx] = pk2(ha, hb);
                xlU[idx] = pk2(__float2bfloat16_rn(a - __bfloat162float(ha)),
                               __float2bfloat16_rn(b - __bfloat162float(hb)));
            }
        };
        auto cpB = [&](int c) {
            const char* src = (const char*)(pB + (size_t)(j * KST + c * 16) * 128);
            char* dst = (char*)(Bb + (size_t)(c % 3) * 2048);
            #pragma unroll
            for (int i = 0; i < 8; i++) {
                int e = (p + 256 * i) * 16;
                cpasync16(smem_u32(dst + e), src + e);
            }
            CP_COMMIT();
        };

        ldgx(0);
        cpB(0); cpB(1);
        stsx(0);
        ldgx(1);
        CP_WAITG(1);
        __syncthreads();
        for (int c = 0; c < NC; c++) {
            if (c + 1 < NC) {
                stsx(c + 1);
                if (c + 2 < NC) ldgx(c + 2);
            }
            if (c + 2 < NC) { cpB(c + 2); CP_WAITG(1); }
            else if (c + 1 < NC) CP_WAITG(0);
            __syncthreads();
        }
    } else {
        const int w = tid >> 5, lane = tid & 31;
        const int mi = w & 1, g = w >> 1;
        const int t4 = lane >> 2, q = lane & 3;
        const int r0 = mi * 16 + t4;
        const uint4* xh4 = (const uint4*)(dsm + OFF_XH);
        const uint4* xl4 = (const uint4*)(dsm + OFF_XL);
        float acc[6][4];
        #pragma unroll
        for (int a = 0; a < 6; a++)
            #pragma unroll
            for (int i = 0; i < 4; i++) acc[a][i] = 0.f;
        __syncthreads();
        for (int c = 0; c < NC; c++) {
            const uint4* Bw = Bb + (c % 3) * 2048 + g * 32 + lane;
            const uint4* xhb = xh4 + (c & 1) * 1024 + mi * 512 + lane;
            const uint4* xlb = xl4 + (c & 1) * 1024 + mi * 512 + lane;
            #pragma unroll
            for (int ksg = 0; ksg < 16; ksg++) {
                uint4 A = xhb[ksg * 32];
                uint4 L = xlb[ksg * 32];
                uint4 B = Bw[ksg * 128];
                float* a0 = acc[(ksg & 1) * 3];
                mma16816(a0,     A.x, A.y, A.z, A.w, B.x, B.y);
                mma16816(a0 + 4, L.x, L.y, L.z, L.w, B.x, B.y);
                mma16816(a0 + 8, A.x, A.y, A.z, A.w, B.z, B.w);
            }
            __syncthreads();
        }
        float d0 = 0.f, d1 = 0.f, d2 = 0.f, d3 = 0.f;
        #pragma unroll
        for (int a = 0; a < 6; a++) {
            d0 += acc[a][0]; d1 += acc[a][1]; d2 += acc[a][2]; d3 += acc[a][3];
        }
        zf[r0 * 32 + g * 8 + 2 * q]           = d0;
        zf[r0 * 32 + g * 8 + 2 * q + 1]       = d1;
        zf[(r0 + 8) * 32 + g * 8 + 2 * q]     = d2;
        zf[(r0 + 8) * 32 + g * 8 + 2 * q + 1] = d3;
    }
    __syncthreads();
}

// ---------------- persistent decoder kernel ----------------
__global__ __launch_bounds__(NTHR, 1) void decoder_persist(
    const float* __restrict__ memory,
    const float* __restrict__ l0b, const float* __restrict__ l1b,
    const float* __restrict__ qw, const float* __restrict__ qb,
    const float* __restrict__ vw, const float* __restrict__ vb,
    const float* __restrict__ cw, const float* __restrict__ cb,
    const float* __restrict__ ldw, const float* __restrict__ ldb,
    float* __restrict__ out_align) {
    extern __shared__ char dsm[];
    float* zf = (float*)(dsm + OFF_ZF);
    float* keys_s = (float*)(dsm + OFF_KEYS);
    AttC* sc = (AttC*)dsm;
    AttD* sd = (AttD*)dsm;
    const int j = blockIdx.x;
    const int tid = threadIdx.x;
    const int ab = j >> 2, ach = j & 3;

    // barrier generation base carries across graph replays (own word)
    unsigned gen;
    asm volatile("ld.acquire.gpu.u32 %0, [%1];" : "=r"(gen) : "l"(&g_relv[j * 32]));

    {   // init state
        int i = j * NTHR + tid;
        if (i < BN * DDIM) {
            g_h0[0][i] = 0.f; g_h0[1][i] = 0.f;
            g_h1[0][i] = 0.f; g_h1[1][i] = 0.f;
        }
        if (i < BN * EDIM) g_ctx[i] = 0.f;
        if (i < BN * TIN)  g_wcum[i] = 0.f;
    }
    for (int i = tid; i < 32 * TIN; i += NTHR)
        keys_s[i] = g_keysT[((size_t)ab * ADIM + ach * 32 + (i >> 8)) * TIN + (i & 255)];

    float c0r = 0.f, c1r = 0.f;
    const int bq = tid >> 3, dd = tid & 7;
    const int du = 8 * j + dd;

    grid_bar(++gen, j, tid);

    for (int t = 0; t < TOUT; t++) {
        const int rb = t & 1, wb = (t + 1) & 1;

        // ---- phase A: LSTM0 GEMM + gates ----
        gemm_mma<1792, 256, 768, PRE>(dsm, j, g_prenet + (size_t)t * BN * PRE,
                                      g_ctx, g_h0[rb], g_pb0, zf);
        if (tid < 256) {
            float zi  = zf[bq * 32 + dd]      + l0b[du];
            float zff = zf[bq * 32 + 8 + dd]  + l0b[1024 + du];
            float zg  = zf[bq * 32 + 16 + dd] + l0b[2048 + du];
            float zo  = zf[bq * 32 + 24 + dd] + l0b[3072 + du];
            float ii = sigmoidf_(zi), ff = sigmoidf_(zff), oo = sigmoidf_(zo);
            c0r = ff * c0r + ii * tanhf(zg);
            __stcg(&g_h0[wb][bq * DDIM + du], oo * tanhf(c0r));
        }
        grid_bar(++gen, j, tid);

        // ---- phase B: LSTM1 GEMM + gates ----
        gemm_mma<2560, 1024, 1536, DDIM>(dsm, j, g_h0[wb], g_ctx, g_h1[rb],
                                         g_pb1, zf);
        if (tid < 256) {
            float zi  = zf[bq * 32 + dd]      + l1b[du];
            float zff = zf[bq * 32 + 8 + dd]  + l1b[1024 + du];
            float zg  = zf[bq * 32 + 16 + dd] + l1b[2048 + du];
            float zo  = zf[bq * 32 + 24 + dd] + l1b[3072 + du];
            float ii = sigmoidf_(zi), ff = sigmoidf_(zff), oo = sigmoidf_(zo);
            c1r = ff * c1r + ii * tanhf(zg);
            float h = oo * tanhf(c1r);
            __stcg(&g_h1[wb][bq * DDIM + du], h);
            g_h1all[((size_t)t * BN + bq) * DDIM + du] = h;
        }
        grid_bar(++gen, j, tid);

        // ---- phase C: attention energies (CTA = b x a-chunk) ----
        {
            const float* h1cur = g_h1[wb];
            for (int i = tid; i < DDIM; i += NTHR)
                sc->h1s[i] = __ldcg(h1cur + ab * DDIM + i);
            for (int i = tid; i < TIN + KSZ - 1; i += NTHR) {
                int jj = i - (KSZ / 2);
                sc->wp[i] = (jj >= 0 && jj < TIN) ? __ldcg(&g_wcum[ab * TIN + jj]) : 0.f;
            }
            for (int i = tid; i < KSZ * NFLT; i += NTHR) sc->cws[i] = cw[i];
            if (tid < NFLT) sc->cbs[tid] = cb[tid];
            for (int i = tid; i < NFLT * 32; i += NTHR)
                sc->ldws[i] = ldw[(i >> 5) * ADIM + ach * 32 + (i & 31)];
            if (tid < 32) {
                sc->ldbs[tid] = ldb[ach * 32 + tid];
                sc->vws[tid]  = vw[ach * 32 + tid];
            }
            __syncthreads();
            {
                int al = tid & 31, part = tid >> 5;
                float a0 = 0.f;
                int k0 = part * 64;
                #pragma unroll 8
                for (int k = k0; k < k0 + 64; k++)
                    a0 += sc->h1s[k] * qw[k * ADIM + ach * 32 + al];
                sc->qred[part][al] = a0;
            }
            {
                int ti = tid & 255, fh = tid >> 8;
                float lf[16];
                #pragma unroll
                for (int f = 0; f < 16; f++) lf[f] = sc->cbs[fh * 16 + f];
                for (int jk = 0; jk < KSZ; jk++) {
                    float w = sc->wp[ti + jk];
                    #pragma unroll
                    for (int f = 0; f < 16; f++)
                        lf[f] += w * sc->cws[jk * NFLT + fh * 16 + f];
                }
                #pragma unroll
                for (int f = 0; f < 16; f++) sc->loc[ti][fh * 16 + f] = lf[f];
            }
            __syncthreads();
            if (tid < 32) {
                float s = 0.f;
                #pragma unroll
                for (int p = 0; p < 16; p++) s += sc->qred[p][tid];
                sc->qp[tid] = s + qb[ach * 32 + tid];
            }
            __syncthreads();
            {
                int ti = tid & 255, ah = tid >> 8;
                float locv[NFLT];
                #pragma unroll
                for (int f = 0; f < NFLT; f++) locv[f] = sc->loc[ti][f];
                float e = 0.f;
                #pragma unroll 4
                for (int al16 = 0; al16 < 16; al16++) {
                    int al = ah * 16 + al16;
                    float s = sc->qp[al] + keys_s[al * TIN + ti] + sc->ldbs[al];
                    #pragma unroll
                    for (int f = 0; f < NFLT; f++) s += locv[f] * sc->ldws[f * 32 + al];
                    float u = __expf(-2.f * fabsf(s));
                    float th = __fdividef(1.f - u, 1.f + u);
                    e += copysignf(th, s) * sc->vws[al];
                }
                sc->es[ah][ti] = e;
            }
            __syncthreads();
            if (tid < 256)
                __stcg(&g_epart[(ach * BN + ab) * TIN + tid],
                       sc->es[0][tid] + sc->es[1][tid]);
        }
        grid_bar(++gen, j, tid);

        // ---- phase D: softmax + context (CTA = b x E-chunk) ----
        {
            const int ec = ach;
            float ev = 0.f, ex = 0.f;
            if (tid < 256) {
                ev = vb[0] + g_maskneg[ab * TIN + tid];
                #pragma unroll
                for (int ac = 0; ac < 4; ac++)
                    ev += __ldcg(&g_epart[(ac * BN + ab) * TIN + tid]);
                sd->red[tid] = ev;
            }
            __syncthreads();
            for (int s = 128; s > 0; s >>= 1) {
                if (tid < s) sd->red[tid] = fmaxf(sd->red[tid], sd->red[tid + s]);
                __syncthreads();
            }
            float mx = sd->red[0];
            __syncthreads();
            if (tid < 256) { ex = expf(ev - mx); sd->red[tid] = ex; }
            __syncthreads();
            for (int s = 128; s > 0; s >>= 1) {
                if (tid < s) sd->red[tid] += sd->red[tid + s];
                __syncthreads();
            }
            float inv = 1.f / sd->red[0];
            __syncthreads();
            if (tid < 256) {
                float w = ex * inv;
                sd->ws[tid] = w;
                if (ec == 0) {
                    __stcg(&g_wcum[ab * TIN + tid],
                           __ldcg(&g_wcum[ab * TIN + tid]) + w);
                    out_align[((size_t)ab * TOUT + t) * TIN + tid] = w;
                }
            }
            __syncthreads();
            {
                int cl = tid & 127, q = tid >> 7;
                float acc = 0.f;
                #pragma unroll 4
                for (int tt = q * 64; tt < q * 64 + 64; tt++)
                    acc += sd->ws[tt] *
                           memory[((size_t)ab * TIN + tt) * EDIM + ec * 128 + cl];
                sd->cred[q][cl] = acc;
                __syncthreads();
                if (tid < 128) {
                    float cv = sd->cred[0][tid] + sd->cred[1][tid] +
                               sd->cred[2][tid] + sd->cred[3][tid];
                    __stcg(&g_ctx[ab * EDIM + ec * 128 + tid], cv);
                    g_ctxall[((size_t)t * BN + ab) * EDIM + ec * 128 + tid] = cv;
                }
            }
        }
        grid_bar(++gen, j, tid);
    }
}

// ---------------- prenet (+ mask build in block 0) ----------------
__global__ void prenet_kernel(const float* __restrict__ targets,
                              const float* __restrict__ w1, const float* __restrict__ b1,
                              const float* __restrict__ w2, const float* __restrict__ b2,
                              const unsigned char* __restrict__ mask) {
    int bid = blockIdx.x;
    int t = bid >> 5, b = bid & 31;
    __shared__ float xin[NMEL];
    __shared__ float h[PRE];
    __shared__ int s_has;
    int tid = threadIdx.x;
    if (tid < NMEL) xin[tid] = (t == 0) ? 0.f : targets[(b * TOUT + (t - 1)) * NMEL + tid];
    __syncthreads();
    float acc = b1[tid];
    #pragma unroll 8
    for (int k = 0; k < NMEL; k++) acc += xin[k] * w1[k * PRE + tid];
    h[tid] = fmaxf(acc, 0.f);
    __syncthreads();
    float acc2 = b2[tid];
    #pragma unroll 8
    for (int k = 0; k < PRE; k++) acc2 += h[k] * w2[k * PRE + tid];
    g_prenet[(t * BN + b) * PRE + tid] = fmaxf(acc2, 0.f);

    if (bid == 0) {
        if (tid == 0) s_has = 0;
        __syncthreads();
        int local = 0;
        for (int i = tid; i < BN * TIN; i += 256)
            if ((i & 3) != 0 && mask[i] != 0) local = 1;
        if (local) atomicOr(&s_has, 1);
        __syncthreads();
        bool is_u8 = (s_has != 0);
        const int* mi = (const int*)mask;
        for (int i = tid; i < BN * TIN; i += 256) {
            int v = is_u8 ? (int)mask[i] : mi[i];
            g_maskneg[i] = v ? 0.f : -1e9f;
        }
    }
}

// ---------------- keys projection ----------------
__global__ void keys_kernel(const float* __restrict__ memory,
                            const float* __restrict__ mw, const float* __restrict__ mb) {
    int bid = blockIdx.x;
    int b = bid >> 8, t = bid & 255;
    __shared__ float x[EDIM];
    int tid = threadIdx.x;
    for (int i = tid; i < EDIM; i += 128) x[i] = memory[(b * TIN + t) * EDIM + i];
    __syncthreads();
    float acc = mb[tid];
    #pragma unroll 8
    for (int k = 0; k < EDIM; k++) acc += x[k] * mw[k * ADIM + tid];
    g_keysT[(b * ADIM + tid) * TIN + t] = acc;
}

// ---------------- output projections ----------------
__global__ void proj_kernel(const float* __restrict__ pw, const float* __restrict__ pb,
                            const float* __restrict__ gw, const float* __restrict__ gb,
                            float* __restrict__ out_mel, float* __restrict__ out_gate) {
    int bid = blockIdx.x;
    int t = bid >> 5, b = bid & 31;
    __shared__ float xo[DDIM + EDIM];
    int tid = threadIdx.x;
    for (int i = tid; i < DDIM; i += 128) xo[i] = g_h1all[(size_t)(t * BN + b) * DDIM + i];
    for (int i = tid; i < EDIM; i += 128) xo[DDIM + i] = g_ctxall[(size_t)(t * BN + b) * EDIM + i];
    __syncthreads();
    if (tid < NMEL) {
        float acc = pb[tid];
        #pragma unroll 8
        for (int k = 0; k < DDIM + EDIM; k++) acc += xo[k] * pw[k * NMEL + tid];
        out_mel[(size_t)(b * TOUT + t) * NMEL + tid] = acc;
    } else if (tid == NMEL) {
        float acc = gb[0];
        for (int k = 0; k < DDIM + EDIM; k++) acc += xo[k] * gw[k];
        out_gate[b * TOUT + t] = acc;
    }
}

// ---------------- launcher ----------------
extern "C" void kernel_launch(void* const* d_in, const int* in_sizes, int n_in,
                              void* d_out, int out_size) {
    (void)in_sizes; (void)n_in; (void)out_size;
    const float* memory  = (const float*)d_in[0];
    const float* targets = (const float*)d_in[1];
    const unsigned char* mask = (const unsigned char*)d_in[2];
    const float* p1w = (const float*)d_in[3];
    const float* p1b = (const float*)d_in[4];
    const float* p2w = (const float*)d_in[5];
    const float* p2b = (const float*)d_in[6];
    const float* l0k = (const float*)d_in[7];
    const float* l0r = (const float*)d_in[8];
    const float* l0b = (const float*)d_in[9];
    const float* l1k = (const float*)d_in[10];
    const float* l1r = (const float*)d_in[11];
    const float* l1b = (const float*)d_in[12];
    const float* qw  = (const float*)d_in[13];
    const float* qb  = (const float*)d_in[14];
    const float* mw  = (const float*)d_in[15];
    const float* mb  = (const float*)d_in[16];
    const float* vw  = (const float*)d_in[17];
    const float* vb  = (const float*)d_in[18];
    const float* ccw = (const float*)d_in[19];
    const float* ccb = (const float*)d_in[20];
    const float* ldw = (const float*)d_in[21];
    const float* ldb = (const float*)d_in[22];
    const float* pw  = (const float*)d_in[23];
    const float* pb  = (const float*)d_in[24];
    const float* gw  = (const float*)d_in[25];
    const float* gb  = (const float*)d_in[26];

    float* out       = (float*)d_out;
    float* out_mel   = out;
    float* out_gate  = out + (size_t)BN * TOUT * NMEL;
    float* out_align = out_gate + (size_t)BN * TOUT;

    static int smem_set = 0;
    if (!smem_set) {
        cudaFuncSetAttribute(decoder_persist,
                             cudaFuncAttributeMaxDynamicSharedMemorySize, DSMEM_BYTES);
        smem_set = 1;
    }

    uint4* pb0;
    uint4* pb1;
    cudaGetSymbolAddress((void**)&pb0, g_pb0);
    cudaGetSymbolAddress((void**)&pb1, g_pb1);

    pack_all_kernel<<<(KST0 + KST1) * 32, 256>>>(l0k, l0r, l1k, l1r, pb0, pb1);
    prenet_kernel<<<TOUT * BN, 256>>>(targets, p1w, p1b, p2w, p2b, mask);
    keys_kernel<<<BN * TIN, 128>>>(memory, mw, mb);
    decoder_persist<<<NCTA, NTHR, DSMEM_BYTES>>>(memory, l0b, l1b, qw, qb, vw, vb,
                                                 ccw, ccb, ldw, ldb, out_align);
    proj_kernel<<<TOUT * BN, 128>>>(pw, pb, gw, gb, out_mel, out_gate);
}

// round 12
// speedup vs baseline: 1.3420x; 1.3420x over previous
#include <cuda_runtime.h>
#include <cuda_bf16.h>
#include <math.h>
#include <string.h>

#define BN 32
#define TIN 256
#define TOUT 400
#define EDIM 512
#define ADIM 128
#define NFLT 32
#define KSZ 31
#define PRE 256
#define DDIM 1024
#define NMEL 80
#define ZN 4096
#define NCTA 128
#define NTHR 1024
#define CHUNKK 256
#define KST0 112
#define KST1 160

// dynamic smem layout
#define OFF_BB 0              // 3 * 32768 B buffers
#define OFF_XH 98304          // 2 * 16384 A-hi (fragment order)
#define OFF_XL 131072         // 2 * 16384 A-lo
#define OFF_ZF 163840         // 2 slabs * 4096
#define OFF_KEYS 172032       // 32 * 256 * 4 persistent keys slice
#define DSMEM_BYTES 204800

// ---------------- persistent device scratch ----------------
__device__ float g_prenet[TOUT * BN * PRE];
__device__ float g_keysT[BN * ADIM * TIN];
__device__ float g_maskneg[BN * TIN];
__device__ float g_h0[2][BN * DDIM];
__device__ float g_h1[2][BN * DDIM];
__device__ float g_ctx[BN * EDIM];
__device__ float g_wcum[BN * TIN];
__device__ float g_epart[4 * BN * TIN];
__device__ float g_h1all[TOUT * BN * DDIM];
__device__ float g_ctxall[TOUT * BN * EDIM];
__device__ unsigned g_flags[NCTA * 32];
__device__ unsigned g_relv[NCTA * 32];
__device__ uint4 g_pb0[(size_t)NCTA * KST0 * 4 * 32];
__device__ uint4 g_pb1[(size_t)NCTA * KST1 * 4 * 32];

__device__ __forceinline__ float sigmoidf_(float x) { return 1.f / (1.f + expf(-x)); }

__device__ __forceinline__ unsigned smem_u32(const void* p) {
    unsigned a;
    asm("{ .reg .u64 t; cvta.to.shared.u64 t, %1; cvt.u32.u64 %0, t; }"
        : "=r"(a) : "l"(p));
    return a;
}
__device__ __forceinline__ void cpasync16(unsigned dst, const void* src) {
    asm volatile("cp.async.cg.shared.global [%0], [%1], 16;" :: "r"(dst), "l"(src));
}
#define CP_COMMIT() asm volatile("cp.async.commit_group;" ::: "memory")
#define CP_WAITG(n) asm volatile("cp.async.wait_group %0;" :: "n"(n) : "memory")

__device__ __forceinline__ unsigned pk2(__nv_bfloat16 a, __nv_bfloat16 b) {
    __nv_bfloat162 t(a, b);
    unsigned r;
    memcpy(&r, &t, 4);
    return r;
}
__device__ __forceinline__ void mma16816(float* d, unsigned a0, unsigned a1,
                                         unsigned a2, unsigned a3,
                                         unsigned b0, unsigned b1) {
    asm volatile("mma.sync.aligned.m16n8k16.row.col.f32.bf16.bf16.f32 "
                 "{%0,%1,%2,%3}, {%4,%5,%6,%7}, {%8,%9}, {%0,%1,%2,%3};"
                 : "+f"(d[0]), "+f"(d[1]), "+f"(d[2]), "+f"(d[3])
                 : "r"(a0), "r"(a1), "r"(a2), "r"(a3), "r"(b0), "r"(b1));
}

// ---------------- contention-free grid barrier ----------------
__device__ __forceinline__ void grid_bar(unsigned gen, int j, int tid) {
    __syncthreads();
    if (j == 0) {
        if (tid >= 1 && tid < NCTA) {
            unsigned v;
            do {
                asm volatile("ld.acquire.gpu.u32 %0, [%1];"
                             : "=r"(v) : "l"(&g_flags[tid * 32]));
            } while (v != gen);
        }
        __syncthreads();
        if (tid == 0) asm volatile("fence.acq_rel.gpu;" ::: "memory");
        __syncthreads();
        if (tid < NCTA)
            asm volatile("st.release.gpu.u32 [%0], %1;"
                         :: "l"(&g_relv[tid * 32]), "r"(gen) : "memory");
    } else {
        if (tid == 0) {
            asm volatile("fence.acq_rel.gpu;" ::: "memory");
            asm volatile("st.release.gpu.u32 [%0], %1;"
                         :: "l"(&g_flags[j * 32]), "r"(gen) : "memory");
            unsigned v;
            do {
                asm volatile("ld.acquire.gpu.u32 %0, [%1];"
                             : "=r"(v) : "l"(&g_relv[j * 32]));
            } while (v != gen);
        }
        __syncthreads();
    }
}

// ---------------- attention smem structs (alias GEMM region) ------------
struct AttC {
    float h1s[DDIM];
    float wp[TIN + KSZ];
    float cws[KSZ * NFLT];
    float cbs[NFLT];
    float ldws[NFLT * 32];
    float ldbs[32], vws[32];
    float qred[32][32];
    float qp[32];
    float es[4][TIN];
    float loc[TIN][NFLT + 1];
};
struct AttD { float red[256]; float ws[256]; float cred[8][128]; };

// ---------------- combined weight pack ----------------
__device__ void pack_tile(const float* __restrict__ wK, const float* __restrict__ wR,
                          int KST, int KB1, uint4* __restrict__ out,
                          int ks, int nb, float (*w)[128]) {
    int k0 = ks * 16;
    const float* W = (k0 < KB1) ? wK + (size_t)k0 * ZN : wR + (size_t)(k0 - KB1) * ZN;
    int N0 = nb * 128;
    for (int i = threadIdx.x; i < 2048; i += 256)
        w[i >> 7][i & 127] = W[(size_t)(i >> 7) * ZN + N0 + (i & 127)];
    __syncthreads();
    int g = N0 >> 10, jbase = (N0 & 1023) >> 3;
    for (int s = threadIdx.x; s < 512; s += 256) {
        int jl = s >> 5, lane = s & 31;
        int q = lane & 3, t4 = lane >> 2;
        int n = jl * 8 + t4;
        float v0 = w[2 * q][n], v1 = w[2 * q + 1][n];
        float v2 = w[2 * q + 8][n], v3 = w[2 * q + 9][n];
        __nv_bfloat16 h0 = __float2bfloat16_rn(v0), h1 = __float2bfloat16_rn(v1);
        __nv_bfloat16 h2 = __float2bfloat16_rn(v2), h3 = __float2bfloat16_rn(v3);
        unsigned bh0 = pk2(h0, h1), bh1 = pk2(h2, h3);
        unsigned bl0 = pk2(__float2bfloat16_rn(v0 - __bfloat162float(h0)),
                           __float2bfloat16_rn(v1 - __bfloat162float(h1)));
        unsigned bl1 = pk2(__float2bfloat16_rn(v2 - __bfloat162float(h2)),
                           __float2bfloat16_rn(v3 - __bfloat162float(h3)));
        int jj = jbase + jl;
        out[((size_t)(jj * KST + ks) * 4 + g) * 32 + lane] = make_uint4(bh0, bh1, bl0, bl1);
    }
}

__global__ void pack_all_kernel(const float* __restrict__ l0k, const float* __restrict__ l0r,
                                const float* __restrict__ l1k, const float* __restrict__ l1r,
                                uint4* __restrict__ o0, uint4* __restrict__ o1) {
    __shared__ float w[16][128];
    int bid = blockIdx.x;
    if (bid < KST0 * 32)
        pack_tile(l0k, l0r, KST0, 768, o0, bid % KST0, bid / KST0, w);
    else {
        bid -= KST0 * 32;
        pack_tile(l1k, l1r, KST1, 1536, o1, bid % KST1, bid / KST1, w);
    }
}

// ---------------- bf16 MMA GEMM, 32 warps: 16 consumers + 16 producers ------
template <int KTOT, int KB0, int KB1, int SA>
__device__ __forceinline__ void gemm_mma(char* dsm, int j,
                                         const float* __restrict__ xA,
                                         const float* __restrict__ xB,
                                         const float* __restrict__ xC,
                                         const uint4* __restrict__ pB,
                                         float* __restrict__ zf) {
    constexpr int NC = KTOT / CHUNKK;
    constexpr int KST = KTOT / 16;
    const int tid = threadIdx.x;
    uint4* Bb = (uint4*)(dsm + OFF_BB);
    unsigned* xhU = (unsigned*)(dsm + OFF_XH);
    unsigned* xlU = (unsigned*)(dsm + OFF_XL);

    if (tid >= 512) {
        // ---- producers: 512 threads, 16 k-floats each ----
        const int p = tid - 512;
        const int row = p >> 4, kseg = p & 15;
        const int mi = row >> 4, rloc = row & 15, t4 = rloc & 7, rbit = rloc >> 3;
        float4 xr[4];
        auto ldgx = [&](int c) {
            int k0 = c * CHUNKK + kseg * 16;
            const float* s;
            if (k0 < KB0)      s = xA + row * SA + k0;
            else if (k0 < KB1) s = xB + row * EDIM + (k0 - KB0);
            else               s = xC + row * DDIM + (k0 - KB1);
            #pragma unroll
            for (int i = 0; i < 4; i++) xr[i] = __ldcg((const float4*)s + i);
        };
        auto stsx = [&](int c) {
            int boff = (c & 1) * 4096;
            const float* fv = (const float*)xr;
            #pragma unroll
            for (int u = 0; u < 8; u++) {
                int k2 = kseg * 8 + u;
                int ksg = k2 >> 3, p8 = k2 & 7;
                int q = p8 & 3, kh = p8 >> 2;
                int idx = boff + (((mi * 16 + ksg) * 32) + t4 * 4 + q) * 4 +
                          (rbit | (kh << 1));
                float a = fv[2 * u], b = fv[2 * u + 1];
                __nv_bfloat16 ha = __float2bfloat16_rn(a), hb = __float2bfloat16_rn(b);
                xhU[idx] = pk2(ha, hb);
                xlU[idx] = pk2(__float2bfloat16_rn(a - __bfloat162float(ha)),
                               __float2bfloat16_rn(b - __bfloat162float(hb)));
            }
        };
        auto cpB = [&](int c) {
            const char* src = (const char*)(pB + (size_t)(j * KST + c * 16) * 128);
            char* dst = (char*)(Bb + (size_t)(c % 3) * 2048);
            #pragma unroll
            for (int i = 0; i < 4; i++) {
                int e = (p + 512 * i) * 16;
                cpasync16(smem_u32(dst + e), src + e);
            }
            CP_COMMIT();
        };

        ldgx(0);
        cpB(0); cpB(1);
        stsx(0);
        ldgx(1);
        CP_WAITG(1);
        __syncthreads();
        for (int c = 0; c < NC; c++) {
            if (c + 1 < NC) {
                stsx(c + 1);
                if (c + 2 < NC) ldgx(c + 2);
            }
            if (c + 2 < NC) { cpB(c + 2); CP_WAITG(1); }
            else if (c + 1 < NC) CP_WAITG(0);
            __syncthreads();
        }
    } else {
        // ---- consumers: 16 warps = (mi, g, ksg-parity) ----
        const int w = tid >> 5, lane = tid & 31;
        const int mi = w & 1, g = (w >> 1) & 3, kp = w >> 3;
        const int t4 = lane >> 2, q = lane & 3;
        const int r0 = mi * 16 + t4;
        const uint4* xh4 = (const uint4*)(dsm + OFF_XH);
        const uint4* xl4 = (const uint4*)(dsm + OFF_XL);
        float acc[6][4];
        #pragma unroll
        for (int a = 0; a < 6; a++)
            #pragma unroll
            for (int i = 0; i < 4; i++) acc[a][i] = 0.f;
        __syncthreads();
        for (int c = 0; c < NC; c++) {
            const uint4* Bw = Bb + (c % 3) * 2048 + g * 32 + lane;
            const uint4* xhb = xh4 + (c & 1) * 1024 + mi * 512 + lane;
            const uint4* xlb = xl4 + (c & 1) * 1024 + mi * 512 + lane;
            #pragma unroll
            for (int k8 = 0; k8 < 8; k8++) {
                int ksg = kp * 8 + k8;
                uint4 A = xhb[ksg * 32];
                uint4 L = xlb[ksg * 32];
                uint4 B = Bw[ksg * 128];
                float* a0 = acc[(k8 & 1) * 3];
                mma16816(a0,     A.x, A.y, A.z, A.w, B.x, B.y);
                mma16816(a0 + 4, L.x, L.y, L.z, L.w, B.x, B.y);
                mma16816(a0 + 8, A.x, A.y, A.z, A.w, B.z, B.w);
            }
            __syncthreads();
        }
        float d0 = 0.f, d1 = 0.f, d2 = 0.f, d3 = 0.f;
        #pragma unroll
        for (int a = 0; a < 6; a++) {
            d0 += acc[a][0]; d1 += acc[a][1]; d2 += acc[a][2]; d3 += acc[a][3];
        }
        float* zfp = zf + kp * 1024;
        zfp[r0 * 32 + g * 8 + 2 * q]           = d0;
        zfp[r0 * 32 + g * 8 + 2 * q + 1]       = d1;
        zfp[(r0 + 8) * 32 + g * 8 + 2 * q]     = d2;
        zfp[(r0 + 8) * 32 + g * 8 + 2 * q + 1] = d3;
    }
    __syncthreads();
}

// ---------------- persistent decoder kernel ----------------
__global__ __launch_bounds__(NTHR, 1) void decoder_persist(
    const float* __restrict__ memory,
    const float* __restrict__ l0b, const float* __restrict__ l1b,
    const float* __restrict__ qw, const float* __restrict__ qb,
    const float* __restrict__ vw, const float* __restrict__ vb,
    const float* __restrict__ cw, const float* __restrict__ cb,
    const float* __restrict__ ldw, const float* __restrict__ ldb,
    float* __restrict__ out_align) {
    extern __shared__ char dsm[];
    float* zf = (float*)(dsm + OFF_ZF);
    float* keys_s = (float*)(dsm + OFF_KEYS);
    AttC* sc = (AttC*)dsm;
    AttD* sd = (AttD*)dsm;
    const int j = blockIdx.x;
    const int tid = threadIdx.x;
    const int ab = j >> 2, ach = j & 3;

    unsigned gen;
    asm volatile("ld.acquire.gpu.u32 %0, [%1];" : "=r"(gen) : "l"(&g_relv[j * 32]));

    {   // init state
        int i = j * NTHR + tid;
        if (i < BN * DDIM) {
            g_h0[0][i] = 0.f; g_h0[1][i] = 0.f;
            g_h1[0][i] = 0.f; g_h1[1][i] = 0.f;
        }
        if (i < BN * EDIM) g_ctx[i] = 0.f;
        if (i < BN * TIN)  g_wcum[i] = 0.f;
    }
    for (int i = tid; i < 32 * TIN; i += NTHR)
        keys_s[i] = g_keysT[((size_t)ab * ADIM + ach * 32 + (i >> 8)) * TIN + (i & 255)];

    float c0r = 0.f, c1r = 0.f;
    const int bq = tid >> 3, dd = tid & 7;
    const int du = 8 * j + dd;

    grid_bar(++gen, j, tid);

    for (int t = 0; t < TOUT; t++) {
        const int rb = t & 1, wb = (t + 1) & 1;

        // ---- phase A: LSTM0 GEMM + gates ----
        gemm_mma<1792, 256, 768, PRE>(dsm, j, g_prenet + (size_t)t * BN * PRE,
                                      g_ctx, g_h0[rb], g_pb0, zf);
        if (tid < 256) {
            float zi  = zf[bq * 32 + dd]      + zf[1024 + bq * 32 + dd]      + l0b[du];
            float zff = zf[bq * 32 + 8 + dd]  + zf[1024 + bq * 32 + 8 + dd]  + l0b[1024 + du];
            float zg  = zf[bq * 32 + 16 + dd] + zf[1024 + bq * 32 + 16 + dd] + l0b[2048 + du];
            float zo  = zf[bq * 32 + 24 + dd] + zf[1024 + bq * 32 + 24 + dd] + l0b[3072 + du];
            float ii = sigmoidf_(zi), ff = sigmoidf_(zff), oo = sigmoidf_(zo);
            c0r = ff * c0r + ii * tanhf(zg);
            __stcg(&g_h0[wb][bq * DDIM + du], oo * tanhf(c0r));
        }
        grid_bar(++gen, j, tid);

        // ---- phase B: LSTM1 GEMM + gates ----
        gemm_mma<2560, 1024, 1536, DDIM>(dsm, j, g_h0[wb], g_ctx, g_h1[rb],
                                         g_pb1, zf);
        if (tid < 256) {
            float zi  = zf[bq * 32 + dd]      + zf[1024 + bq * 32 + dd]      + l1b[du];
            float zff = zf[bq * 32 + 8 + dd]  + zf[1024 + bq * 32 + 8 + dd]  + l1b[1024 + du];
            float zg  = zf[bq * 32 + 16 + dd] + zf[1024 + bq * 32 + 16 + dd] + l1b[2048 + du];
            float zo  = zf[bq * 32 + 24 + dd] + zf[1024 + bq * 32 + 24 + dd] + l1b[3072 + du];
            float ii = sigmoidf_(zi), ff = sigmoidf_(zff), oo = sigmoidf_(zo);
            c1r = ff * c1r + ii * tanhf(zg);
            float h = oo * tanhf(c1r);
            __stcg(&g_h1[wb][bq * DDIM + du], h);
            g_h1all[((size_t)t * BN + bq) * DDIM + du] = h;
        }
        grid_bar(++gen, j, tid);

        // ---- phase C: attention energies (CTA = b x a-chunk) ----
        {
            const float* h1cur = g_h1[wb];
            for (int i = tid; i < DDIM; i += NTHR)
                sc->h1s[i] = __ldcg(h1cur + ab * DDIM + i);
            for (int i = tid; i < TIN + KSZ - 1; i += NTHR) {
                int jj = i - (KSZ / 2);
                sc->wp[i] = (jj >= 0 && jj < TIN) ? __ldcg(&g_wcum[ab * TIN + jj]) : 0.f;
            }
            for (int i = tid; i < KSZ * NFLT; i += NTHR) sc->cws[i] = cw[i];
            if (tid < NFLT) sc->cbs[tid] = cb[tid];
            for (int i = tid; i < NFLT * 32; i += NTHR)
                sc->ldws[i] = ldw[(i >> 5) * ADIM + ach * 32 + (i & 31)];
            if (tid < 32) {
                sc->ldbs[tid] = ldb[ach * 32 + tid];
                sc->vws[tid]  = vw[ach * 32 + tid];
            }
            __syncthreads();
            {   // qp partials: 32 parts x 32 k
                int al = tid & 31, part = tid >> 5;
                float a0 = 0.f;
                int k0 = part * 32;
                #pragma unroll 8
                for (int k = k0; k < k0 + 32; k++)
                    a0 += sc->h1s[k] * qw[k * ADIM + ach * 32 + al];
                sc->qred[part][al] = a0;
            }
            {   // conv: thread (ti, fq) does 8 filters
                int ti = tid & 255, fq = tid >> 8;
                float lf[8];
                #pragma unroll
                for (int f = 0; f < 8; f++) lf[f] = sc->cbs[fq * 8 + f];
                for (int jk = 0; jk < KSZ; jk++) {
                    float w = sc->wp[ti + jk];
                    #pragma unroll
                    for (int f = 0; f < 8; f++)
                        lf[f] += w * sc->cws[jk * NFLT + fq * 8 + f];
                }
                #pragma unroll
                for (int f = 0; f < 8; f++) sc->loc[ti][fq * 8 + f] = lf[f];
            }
            __syncthreads();
            if (tid < 32) {
                float s = 0.f;
                #pragma unroll
                for (int p = 0; p < 32; p++) s += sc->qred[p][tid];
                sc->qp[tid] = s + qb[ach * 32 + tid];
            }
            __syncthreads();
            {   // energies: thread (ti, ah) does 8 a's, f-outer accumulation
                int ti = tid & 255, ah = tid >> 8;
                float s[8];
                #pragma unroll
                for (int a8 = 0; a8 < 8; a8++) {
                    int al = ah * 8 + a8;
                    s[a8] = sc->qp[al] + keys_s[al * TIN + ti] + sc->ldbs[al];
                }
                #pragma unroll 4
                for (int f = 0; f < NFLT; f++) {
                    float lf = sc->loc[ti][f];
                    #pragma unroll
                    for (int a8 = 0; a8 < 8; a8++)
                        s[a8] += lf * sc->ldws[f * 32 + ah * 8 + a8];
                }
                float e = 0.f;
                #pragma unroll
                for (int a8 = 0; a8 < 8; a8++) {
                    float u = __expf(-2.f * fabsf(s[a8]));
                    float th = __fdividef(1.f - u, 1.f + u);
                    e += copysignf(th, s[a8]) * sc->vws[ah * 8 + a8];
                }
                sc->es[ah][ti] = e;
            }
            __syncthreads();
            if (tid < 256)
                __stcg(&g_epart[(ach * BN + ab) * TIN + tid],
                       sc->es[0][tid] + sc->es[1][tid] + sc->es[2][tid] + sc->es[3][tid]);
        }
        grid_bar(++gen, j, tid);

        // ---- phase D: softmax + context (CTA = b x E-chunk) ----
        {
            const int ec = ach;
            float ev = 0.f, ex = 0.f;
            if (tid < 256) {
                ev = vb[0] + g_maskneg[ab * TIN + tid];
                #pragma unroll
                for (int ac = 0; ac < 4; ac++)
                    ev += __ldcg(&g_epart[(ac * BN + ab) * TIN + tid]);
                sd->red[tid] = ev;
            }
            __syncthreads();
            for (int s = 128; s > 0; s >>= 1) {
                if (tid < s) sd->red[tid] = fmaxf(sd->red[tid], sd->red[tid + s]);
                __syncthreads();
            }
            float mx = sd->red[0];
            __syncthreads();
            if (tid < 256) { ex = expf(ev - mx); sd->red[tid] = ex; }
            __syncthreads();
            for (int s = 128; s > 0; s >>= 1) {
                if (tid < s) sd->red[tid] += sd->red[tid + s];
                __syncthreads();
            }
            float inv = 1.f / sd->red[0];
            __syncthreads();
            if (tid < 256) {
                float w = ex * inv;
                sd->ws[tid] = w;
                if (ec == 0) {
                    __stcg(&g_wcum[ab * TIN + tid],
                           __ldcg(&g_wcum[ab * TIN + tid]) + w);
                    out_align[((size_t)ab * TOUT + t) * TIN + tid] = w;
                }
            }
            __syncthreads();
            {   // context: 128 cols x 8 t-slices
                int cl = tid & 127, q = tid >> 7;
                float acc = 0.f;
                #pragma unroll 4
                for (int tt = q * 32; tt < q * 32 + 32; tt++)
                    acc += sd->ws[tt] *
                           memory[((size_t)ab * TIN + tt) * EDIM + ec * 128 + cl];
                sd->cred[q][cl] = acc;
                __syncthreads();
                if (tid < 128) {
                    float cv = 0.f;
                    #pragma unroll
                    for (int q2 = 0; q2 < 8; q2++) cv += sd->cred[q2][tid];
                    __stcg(&g_ctx[ab * EDIM + ec * 128 + tid], cv);
                    g_ctxall[((size_t)t * BN + ab) * EDIM + ec * 128 + tid] = cv;
                }
            }
        }
        grid_bar(++gen, j, tid);
    }
}

// ---------------- prenet (+ mask build in block 0) ----------------
__global__ void prenet_kernel(const float* __restrict__ targets,
                              const float* __restrict__ w1, const float* __restrict__ b1,
                              const float* __restrict__ w2, const float* __restrict__ b2,
                              const unsigned char* __restrict__ mask) {
    int bid = blockIdx.x;
    int t = bid >> 5, b = bid & 31;
    __shared__ float xin[NMEL];
    __shared__ float h[PRE];
    __shared__ int s_has;
    int tid = threadIdx.x;
    if (tid < NMEL) xin[tid] = (t == 0) ? 0.f : targets[(b * TOUT + (t - 1)) * NMEL + tid];
    __syncthreads();
    float acc = b1[tid];
    #pragma unroll 8
    for (int k = 0; k < NMEL; k++) acc += xin[k] * w1[k * PRE + tid];
    h[tid] = fmaxf(acc, 0.f);
    __syncthreads();
    float acc2 = b2[tid];
    #pragma unroll 8
    for (int k = 0; k < PRE; k++) acc2 += h[k] * w2[k * PRE + tid];
    g_prenet[(t * BN + b) * PRE + tid] = fmaxf(acc2, 0.f);

    if (bid == 0) {
        if (tid == 0) s_has = 0;
        __syncthreads();
        int local = 0;
        for (int i = tid; i < BN * TIN; i += 256)
            if ((i & 3) != 0 && mask[i] != 0) local = 1;
        if (local) atomicOr(&s_has, 1);
        __syncthreads();
        bool is_u8 = (s_has != 0);
        const int* mi = (const int*)mask;
        for (int i = tid; i < BN * TIN; i += 256) {
            int v = is_u8 ? (int)mask[i] : mi[i];
            g_maskneg[i] = v ? 0.f : -1e9f;
        }
    }
}

// ---------------- keys projection ----------------
__global__ void keys_kernel(const float* __restrict__ memory,
                            const float* __restrict__ mw, const float* __restrict__ mb) {
    int bid = blockIdx.x;
    int b = bid >> 8, t = bid & 255;
    __shared__ float x[EDIM];
    int tid = threadIdx.x;
    for (int i = tid; i < EDIM; i += 128) x[i] = memory[(b * TIN + t) * EDIM + i];
    __syncthreads();
    float acc = mb[tid];
    #pragma unroll 8
    for (int k = 0; k < EDIM; k++) acc += x[k] * mw[k * ADIM + tid];
    g_keysT[(b * ADIM + tid) * TIN + t] = acc;
}

// ---------------- output projections ----------------
__global__ void proj_kernel(const float* __restrict__ pw, const float* __restrict__ pb,
                            const float* __restrict__ gw, const float* __restrict__ gb,
                            float* __restrict__ out_mel, float* __restrict__ out_gate) {
    int bid = blockIdx.x;
    int t = bid >> 5, b = bid & 31;
    __shared__ float xo[DDIM + EDIM];
    int tid = threadIdx.x;
    for (int i = tid; i < DDIM; i += 128) xo[i] = g_h1all[(size_t)(t * BN + b) * DDIM + i];
    for (int i = tid; i < EDIM; i += 128) xo[DDIM + i] = g_ctxall[(size_t)(t * BN + b) * EDIM + i];
    __syncthreads();
    if (tid < NMEL) {
        float acc = pb[tid];
        #pragma unroll 8
        for (int k = 0; k < DDIM + EDIM; k++) acc += xo[k] * pw[k * NMEL + tid];
        out_mel[(size_t)(b * TOUT + t) * NMEL + tid] = acc;
    } else if (tid == NMEL) {
        float acc = gb[0];
        for (int k = 0; k < DDIM + EDIM; k++) acc += xo[k] * gw[k];
        out_gate[b * TOUT + t] = acc;
    }
}

// ---------------- launcher ----------------
extern "C" void kernel_launch(void* const* d_in, const int* in_sizes, int n_in,
                              void* d_out, int out_size) {
    (void)in_sizes; (void)n_in; (void)out_size;
    const float* memory  = (const float*)d_in[0];
    const float* targets = (const float*)d_in[1];
    const unsigned char* mask = (const unsigned char*)d_in[2];
    const float* p1w = (const float*)d_in[3];
    const float* p1b = (const float*)d_in[4];
    const float* p2w = (const float*)d_in[5];
    const float* p2b = (const float*)d_in[6];
    const float* l0k = (const float*)d_in[7];
    const float* l0r = (const float*)d_in[8];
    const float* l0b = (const float*)d_in[9];
    const float* l1k = (const float*)d_in[10];
    const float* l1r = (const float*)d_in[11];
    const float* l1b = (const float*)d_in[12];
    const float* qw  = (const float*)d_in[13];
    const float* qb  = (const float*)d_in[14];
    const float* mw  = (const float*)d_in[15];
    const float* mb  = (const float*)d_in[16];
    const float* vw  = (const float*)d_in[17];
    const float* vb  = (const float*)d_in[18];
    const float* ccw = (const float*)d_in[19];
    const float* ccb = (const float*)d_in[20];
    const float* ldw = (const float*)d_in[21];
    const float* ldb = (const float*)d_in[22];
    const float* pw  = (const float*)d_in[23];
    const float* pb  = (const float*)d_in[24];
    const float* gw  = (const float*)d_in[25];
    const float* gb  = (const float*)d_in[26];

    float* out       = (float*)d_out;
    float* out_mel   = out;
    float* out_gate  = out + (size_t)BN * TOUT * NMEL;
    float* out_align = out_gate + (size_t)BN * TOUT;

    static int smem_set = 0;
    if (!smem_set) {
        cudaFuncSetAttribute(decoder_persist,
                             cudaFuncAttributeMaxDynamicSharedMemorySize, DSMEM_BYTES);
        smem_set = 1;
    }

    uint4* pb0;
    uint4* pb1;
    cudaGetSymbolAddress((void**)&pb0, g_pb0);
    cudaGetSymbolAddress((void**)&pb1, g_pb1);

    pack_all_kernel<<<(KST0 + KST1) * 32, 256>>>(l0k, l0r, l1k, l1r, pb0, pb1);
    prenet_kernel<<<TOUT * BN, 256>>>(targets, p1w, p1b, p2w, p2b, mask);
    keys_kernel<<<BN * TIN, 128>>>(memory, mw, mb);
    decoder_persist<<<NCTA, NTHR, DSMEM_BYTES>>>(memory, l0b, l1b, qw, qb, vw, vb,
                                                 ccw, ccb, ldw, ldb, out_align);
    proj_kernel<<<TOUT * BN, 128>>>(pw, pb, gw, gb, out_mel, out_gate);
}

// round 13
// speedup vs baseline: 1.6935x; 1.2620x over previous
#include <cuda_runtime.h>
#include <cuda_bf16.h>
#include <math.h>
#include <string.h>

#define BN 32
#define TIN 256
#define TOUT 400
#define EDIM 512
#define ADIM 128
#define NFLT 32
#define KSZ 31
#define PRE 256
#define DDIM 1024
#define NMEL 80
#define ZN 4096
#define NCTA 128
#define NTHR 1024
#define KST0 112
#define KST1 160

// dynamic smem layout (3-deep B + 3-deep xh/xl + zf)
#define OFF_BB 0              // 3 * 32768
#define OFF_XH 98304          // 3 * 16384
#define OFF_XL 147456         // 3 * 16384
#define OFF_ZF 196608         // 2 slabs * 4096
#define DSMEM_BYTES 204800

// ---------------- persistent device scratch ----------------
__device__ float g_keysT[BN * ADIM * TIN];
__device__ float g_maskneg[BN * TIN];
__device__ float g_h1[2][BN * DDIM];
__device__ float g_wcum[BN * TIN];
__device__ float g_epart[4 * BN * TIN];
__device__ float g_h1all[TOUT * BN * DDIM];
__device__ float g_ctxall[TOUT * BN * EDIM];
__device__ unsigned g_flags[NCTA * 32];
__device__ unsigned g_relv[NCTA * 32];
// x operands resident as bf16 hi/lo MMA fragments (uint-packed pairs)
__device__ unsigned g_pnh[(size_t)TOUT * 4096], g_pnl[(size_t)TOUT * 4096];
__device__ unsigned g_h0h[2][4 * 4096], g_h0l[2][4 * 4096];
__device__ unsigned g_cxh[2][2 * 4096], g_cxl[2][2 * 4096];
__device__ unsigned g_h1h[2][4 * 4096], g_h1l[2][4 * 4096];
__device__ uint4 g_pb0[(size_t)NCTA * KST0 * 4 * 32];
__device__ uint4 g_pb1[(size_t)NCTA * KST1 * 4 * 32];

__device__ __forceinline__ float sigmoidf_(float x) { return 1.f / (1.f + expf(-x)); }

__device__ __forceinline__ unsigned smem_u32(const void* p) {
    unsigned a;
    asm("{ .reg .u64 t; cvta.to.shared.u64 t, %1; cvt.u32.u64 %0, t; }"
        : "=r"(a) : "l"(p));
    return a;
}
__device__ __forceinline__ void cpasync16(unsigned dst, const void* src) {
    asm volatile("cp.async.cg.shared.global [%0], [%1], 16;" :: "r"(dst), "l"(src));
}
#define CP_COMMIT() asm volatile("cp.async.commit_group;" ::: "memory")
#define CP_WAITG(n) asm volatile("cp.async.wait_group %0;" :: "n"(n) : "memory")

__device__ __forceinline__ unsigned pk2(__nv_bfloat16 a, __nv_bfloat16 b) {
    __nv_bfloat162 t(a, b);
    unsigned r;
    memcpy(&r, &t, 4);
    return r;
}
__device__ __forceinline__ void mma16816(float* d, unsigned a0, unsigned a1,
                                         unsigned a2, unsigned a3,
                                         unsigned b0, unsigned b1) {
    asm volatile("mma.sync.aligned.m16n8k16.row.col.f32.bf16.bf16.f32 "
                 "{%0,%1,%2,%3}, {%4,%5,%6,%7}, {%8,%9}, {%0,%1,%2,%3};"
                 : "+f"(d[0]), "+f"(d[1]), "+f"(d[2]), "+f"(d[3])
                 : "r"(a0), "r"(a1), "r"(a2), "r"(a3), "r"(b0), "r"(b1));
}

// fragment store: one fp32 value -> hi/lo bf16 at its MMA-fragment position.
// layout (uints within chunk): mi*2048 + ksg*128 + lane*4 + (rbit + 2*kh), half picks bf16.
__device__ __forceinline__ void frag_store(unsigned* bh, unsigned* bl,
                                           int row, int c, int kk, float v) {
    int rl = row & 15;
    int mi = row >> 4, t4 = rl & 7, rbit = rl >> 3;
    int k2 = kk >> 1, half = kk & 1;
    int ksg = k2 >> 3, p8 = k2 & 7, q = p8 & 3, kh = p8 >> 2;
    int uidx = c * 4096 + mi * 2048 + ksg * 128 + (t4 * 4 + q) * 4 + rbit + 2 * kh;
    __nv_bfloat16 hi = __float2bfloat16_rn(v);
    __nv_bfloat16 lo = __float2bfloat16_rn(v - __bfloat162float(hi));
    ((__nv_bfloat16*)(bh + uidx))[half] = hi;
    ((__nv_bfloat16*)(bl + uidx))[half] = lo;
}

// ---------------- contention-free grid barrier ----------------
__device__ __forceinline__ void grid_bar(unsigned gen, int j, int tid) {
    __syncthreads();
    if (j == 0) {
        if (tid >= 1 && tid < NCTA) {
            unsigned v;
            do {
                asm volatile("ld.acquire.gpu.u32 %0, [%1];"
                             : "=r"(v) : "l"(&g_flags[tid * 32]));
            } while (v != gen);
        }
        __syncthreads();
        if (tid == 0) asm volatile("fence.acq_rel.gpu;" ::: "memory");
        __syncthreads();
        if (tid < NCTA)
            asm volatile("st.release.gpu.u32 [%0], %1;"
                         :: "l"(&g_relv[tid * 32]), "r"(gen) : "memory");
    } else {
        if (tid == 0) {
            asm volatile("fence.acq_rel.gpu;" ::: "memory");
            asm volatile("st.release.gpu.u32 [%0], %1;"
                         :: "l"(&g_flags[j * 32]), "r"(gen) : "memory");
            unsigned v;
            do {
                asm volatile("ld.acquire.gpu.u32 %0, [%1];"
                             : "=r"(v) : "l"(&g_relv[j * 32]));
            } while (v != gen);
        }
        __syncthreads();
    }
}

// ---------------- attention smem structs (alias GEMM region) ------------
struct AttC {
    float h1s[DDIM];
    float wp[TIN + KSZ];
    float cws[KSZ * NFLT];
    float cbs[NFLT];
    float ldws[NFLT * 32];
    float ldbs[32], vws[32];
    float qred[32][32];
    float qp[32];
    float es[4][TIN];
    float loc[TIN][NFLT + 1];
};
struct AttD { float red[256]; float ws[256]; float cred[8][128]; };

// ---------------- combined weight pack ----------------
__device__ void pack_tile(const float* __restrict__ wK, const float* __restrict__ wR,
                          int KST, int KB1, uint4* __restrict__ out,
                          int ks, int nb, float (*w)[128]) {
    int k0 = ks * 16;
    const float* W = (k0 < KB1) ? wK + (size_t)k0 * ZN : wR + (size_t)(k0 - KB1) * ZN;
    int N0 = nb * 128;
    for (int i = threadIdx.x; i < 2048; i += 256)
        w[i >> 7][i & 127] = W[(size_t)(i >> 7) * ZN + N0 + (i & 127)];
    __syncthreads();
    int g = N0 >> 10, jbase = (N0 & 1023) >> 3;
    for (int s = threadIdx.x; s < 512; s += 256) {
        int jl = s >> 5, lane = s & 31;
        int q = lane & 3, t4 = lane >> 2;
        int n = jl * 8 + t4;
        float v0 = w[2 * q][n], v1 = w[2 * q + 1][n];
        float v2 = w[2 * q + 8][n], v3 = w[2 * q + 9][n];
        __nv_bfloat16 h0 = __float2bfloat16_rn(v0), h1 = __float2bfloat16_rn(v1);
        __nv_bfloat16 h2 = __float2bfloat16_rn(v2), h3 = __float2bfloat16_rn(v3);
        unsigned bh0 = pk2(h0, h1), bh1 = pk2(h2, h3);
        unsigned bl0 = pk2(__float2bfloat16_rn(v0 - __bfloat162float(h0)),
                           __float2bfloat16_rn(v1 - __bfloat162float(h1)));
        unsigned bl1 = pk2(__float2bfloat16_rn(v2 - __bfloat162float(h2)),
                           __float2bfloat16_rn(v3 - __bfloat162float(h3)));
        int jj = jbase + jl;
        out[((size_t)(jj * KST + ks) * 4 + g) * 32 + lane] = make_uint4(bh0, bh1, bl0, bl1);
    }
}

__global__ void pack_all_kernel(const float* __restrict__ l0k, const float* __restrict__ l0r,
                                const float* __restrict__ l1k, const float* __restrict__ l1r,
                                uint4* __restrict__ o0, uint4* __restrict__ o1) {
    __shared__ float w[16][128];
    int bid = blockIdx.x;
    if (bid < KST0 * 32)
        pack_tile(l0k, l0r, KST0, 768, o0, bid % KST0, bid / KST0, w);
    else {
        bid -= KST0 * 32;
        pack_tile(l1k, l1r, KST1, 1536, o1, bid % KST1, bid / KST1, w);
    }
}

// ---------------- bf16 MMA GEMM: pure cp.async producers, frag-resident x ---
template <int KTOT, int KST>
__device__ __forceinline__ void gemm_mma(char* dsm, int j, int tid,
                                         const unsigned* shA, const unsigned* slA, int nA,
                                         const unsigned* shB, const unsigned* slB, int nAB,
                                         const unsigned* shC, const unsigned* slC,
                                         const uint4* pB, float* zf) {
    constexpr int NC = KTOT / 256;
    uint4* Bb = (uint4*)(dsm + OFF_BB);
    unsigned* xhU = (unsigned*)(dsm + OFF_XH);
    unsigned* xlU = (unsigned*)(dsm + OFF_XL);

    if (tid >= 512) {
        const int p = tid - 512;
        auto cpAll = [&](int c) {
            const unsigned *sh, *sl;
            if (c < nA)       { sh = shA + (size_t)c * 4096;         sl = slA + (size_t)c * 4096; }
            else if (c < nAB) { sh = shB + (size_t)(c - nA) * 4096;  sl = slB + (size_t)(c - nA) * 4096; }
            else              { sh = shC + (size_t)(c - nAB) * 4096; sl = slC + (size_t)(c - nAB) * 4096; }
            char* dxh = (char*)(xhU + (c % 3) * 4096);
            char* dxl = (char*)(xlU + (c % 3) * 4096);
            char* dB  = (char*)(Bb + (size_t)(c % 3) * 2048);
            const char* srcB = (const char*)(pB + (size_t)(j * KST + c * 16) * 128);
            cpasync16(smem_u32(dxh + p * 16), (const char*)sh + p * 16);
            cpasync16(smem_u32(dxh + (p + 512) * 16), (const char*)sh + (p + 512) * 16);
            cpasync16(smem_u32(dxl + p * 16), (const char*)sl + p * 16);
            cpasync16(smem_u32(dxl + (p + 512) * 16), (const char*)sl + (p + 512) * 16);
            #pragma unroll
            for (int i = 0; i < 4; i++)
                cpasync16(smem_u32(dB + (p + 512 * i) * 16), srcB + (p + 512 * i) * 16);
            CP_COMMIT();
        };
        cpAll(0); cpAll(1);
        for (int c = 0; c < NC; c++) {
            if (c < NC - 1) CP_WAITG(1); else CP_WAITG(0);
            __syncthreads();
            if (c + 2 < NC) cpAll(c + 2);
        }
    } else {
        const int w = tid >> 5, lane = tid & 31;
        const int mi = w & 1, g = (w >> 1) & 3, kp = w >> 3;
        const int t4 = lane >> 2, q = lane & 3;
        const int r0 = mi * 16 + t4;
        const uint4* xh4 = (const uint4*)(dsm + OFF_XH);
        const uint4* xl4 = (const uint4*)(dsm + OFF_XL);
        float acc[6][4];
        #pragma unroll
        for (int a = 0; a < 6; a++)
            #pragma unroll
            for (int i = 0; i < 4; i++) acc[a][i] = 0.f;
        for (int c = 0; c < NC; c++) {
            __syncthreads();
            const uint4* Bw = Bb + (c % 3) * 2048 + g * 32 + lane;
            const uint4* xhb = xh4 + (c % 3) * 1024 + mi * 512 + lane;
            const uint4* xlb = xl4 + (c % 3) * 1024 + mi * 512 + lane;
            #pragma unroll
            for (int k8 = 0; k8 < 8; k8++) {
                int ksg = kp * 8 + k8;
                uint4 A = xhb[ksg * 32];
                uint4 L = xlb[ksg * 32];
                uint4 B = Bw[ksg * 128];
                float* a0 = acc[(k8 & 1) * 3];
                mma16816(a0,     A.x, A.y, A.z, A.w, B.x, B.y);
                mma16816(a0 + 4, L.x, L.y, L.z, L.w, B.x, B.y);
                mma16816(a0 + 8, A.x, A.y, A.z, A.w, B.z, B.w);
            }
        }
        float d0 = 0.f, d1 = 0.f, d2 = 0.f, d3 = 0.f;
        #pragma unroll
        for (int a = 0; a < 6; a++) {
            d0 += acc[a][0]; d1 += acc[a][1]; d2 += acc[a][2]; d3 += acc[a][3];
        }
        float* zfp = zf + kp * 1024;
        zfp[r0 * 32 + g * 8 + 2 * q]           = d0;
        zfp[r0 * 32 + g * 8 + 2 * q + 1]       = d1;
        zfp[(r0 + 8) * 32 + g * 8 + 2 * q]     = d2;
        zfp[(r0 + 8) * 32 + g * 8 + 2 * q + 1] = d3;
    }
    __syncthreads();
}

// ---------------- persistent decoder kernel ----------------
__global__ __launch_bounds__(NTHR, 1) void decoder_persist(
    const float* __restrict__ memory,
    const float* __restrict__ l0b, const float* __restrict__ l1b,
    const float* __restrict__ qw, const float* __restrict__ qb,
    const float* __restrict__ vw, const float* __restrict__ vb,
    const float* __restrict__ cw, const float* __restrict__ cb,
    const float* __restrict__ ldw, const float* __restrict__ ldb,
    float* __restrict__ out_align) {
    extern __shared__ char dsm[];
    float* zf = (float*)(dsm + OFF_ZF);
    AttC* sc = (AttC*)dsm;
    AttD* sd = (AttD*)dsm;
    const int j = blockIdx.x;
    const int tid = threadIdx.x;
    const int ab = j >> 2, ach = j & 3;

    unsigned gen;
    asm volatile("ld.acquire.gpu.u32 %0, [%1];" : "=r"(gen) : "l"(&g_relv[j * 32]));

    {   // init: zero parity-0 fragment buffers + wcum
        int i = j * NTHR + tid;   // 0..131071
        if (i < 4 * 4096) {
            g_h0h[0][i] = 0u; g_h0l[0][i] = 0u;
            g_h1h[0][i] = 0u; g_h1l[0][i] = 0u;
        }
        if (i < 2 * 4096) { g_cxh[0][i] = 0u; g_cxl[0][i] = 0u; }
        if (i < BN * TIN) g_wcum[i] = 0.f;
    }

    float c0r = 0.f, c1r = 0.f;
    const int bq = tid >> 3, dd = tid & 7;
    const int du = 8 * j + dd;

    grid_bar(++gen, j, tid);

    for (int t = 0; t < TOUT; t++) {
        const int rb = t & 1, wb = (t + 1) & 1;

        // ---- phase A: LSTM0 GEMM + gates (h0 written as fragments) ----
        gemm_mma<1792, KST0>(dsm, j, tid,
                             g_pnh + (size_t)t * 4096, g_pnl + (size_t)t * 4096, 1,
                             g_cxh[rb], g_cxl[rb], 3,
                             g_h0h[rb], g_h0l[rb], g_pb0, zf);
        if (tid < 256) {
            float zi  = zf[bq * 32 + dd]      + zf[1024 + bq * 32 + dd]      + l0b[du];
            float zff = zf[bq * 32 + 8 + dd]  + zf[1024 + bq * 32 + 8 + dd]  + l0b[1024 + du];
            float zg  = zf[bq * 32 + 16 + dd] + zf[1024 + bq * 32 + 16 + dd] + l0b[2048 + du];
            float zo  = zf[bq * 32 + 24 + dd] + zf[1024 + bq * 32 + 24 + dd] + l0b[3072 + du];
            float ii = sigmoidf_(zi), ff = sigmoidf_(zff), oo = sigmoidf_(zo);
            c0r = ff * c0r + ii * tanhf(zg);
            frag_store(g_h0h[wb], g_h0l[wb], bq, du >> 8, du & 255, oo * tanhf(c0r));
        }
        grid_bar(++gen, j, tid);

        // ---- phase B: LSTM1 GEMM + gates ----
        gemm_mma<2560, KST1>(dsm, j, tid,
                             g_h0h[wb], g_h0l[wb], 4,
                             g_cxh[rb], g_cxl[rb], 6,
                             g_h1h[rb], g_h1l[rb], g_pb1, zf);
        if (tid < 256) {
            float zi  = zf[bq * 32 + dd]      + zf[1024 + bq * 32 + dd]      + l1b[du];
            float zff = zf[bq * 32 + 8 + dd]  + zf[1024 + bq * 32 + 8 + dd]  + l1b[1024 + du];
            float zg  = zf[bq * 32 + 16 + dd] + zf[1024 + bq * 32 + 16 + dd] + l1b[2048 + du];
            float zo  = zf[bq * 32 + 24 + dd] + zf[1024 + bq * 32 + 24 + dd] + l1b[3072 + du];
            float ii = sigmoidf_(zi), ff = sigmoidf_(zff), oo = sigmoidf_(zo);
            c1r = ff * c1r + ii * tanhf(zg);
            float h = oo * tanhf(c1r);
            frag_store(g_h1h[wb], g_h1l[wb], bq, du >> 8, du & 255, h);
            __stcg(&g_h1[wb][bq * DDIM + du], h);
            g_h1all[((size_t)t * BN + bq) * DDIM + du] = h;
        }
        grid_bar(++gen, j, tid);

        // ---- phase C: attention energies (CTA = b x a-chunk) ----
        {
            const float* h1cur = g_h1[wb];
            for (int i = tid; i < DDIM; i += NTHR)
                sc->h1s[i] = __ldcg(h1cur + ab * DDIM + i);
            for (int i = tid; i < TIN + KSZ - 1; i += NTHR) {
                int jj = i - (KSZ / 2);
                sc->wp[i] = (jj >= 0 && jj < TIN) ? __ldcg(&g_wcum[ab * TIN + jj]) : 0.f;
            }
            for (int i = tid; i < KSZ * NFLT; i += NTHR) sc->cws[i] = cw[i];
            if (tid < NFLT) sc->cbs[tid] = cb[tid];
            for (int i = tid; i < NFLT * 32; i += NTHR)
                sc->ldws[i] = ldw[(i >> 5) * ADIM + ach * 32 + (i & 31)];
            if (tid < 32) {
                sc->ldbs[tid] = ldb[ach * 32 + tid];
                sc->vws[tid]  = vw[ach * 32 + tid];
            }
            __syncthreads();
            {   // qp partials: 32 parts x 32 k
                int al = tid & 31, part = tid >> 5;
                float a0 = 0.f;
                int k0 = part * 32;
                #pragma unroll 8
                for (int k = k0; k < k0 + 32; k++)
                    a0 += sc->h1s[k] * qw[k * ADIM + ach * 32 + al];
                sc->qred[part][al] = a0;
            }
            {   // conv: thread (ti, fq) does 8 filters
                int ti = tid & 255, fq = tid >> 8;
                float lf[8];
                #pragma unroll
                for (int f = 0; f < 8; f++) lf[f] = sc->cbs[fq * 8 + f];
                for (int jk = 0; jk < KSZ; jk++) {
                    float w = sc->wp[ti + jk];
                    #pragma unroll
                    for (int f = 0; f < 8; f++)
                        lf[f] += w * sc->cws[jk * NFLT + fq * 8 + f];
                }
                #pragma unroll
                for (int f = 0; f < 8; f++) sc->loc[ti][fq * 8 + f] = lf[f];
            }
            __syncthreads();
            if (tid < 32) {
                float s = 0.f;
                #pragma unroll
                for (int p = 0; p < 32; p++) s += sc->qred[p][tid];
                sc->qp[tid] = s + qb[ach * 32 + tid];
            }
            __syncthreads();
            {   // energies: thread (ti, ah) does 8 a's; keys direct from L2
                int ti = tid & 255, ah = tid >> 8;
                const float* kb = g_keysT + ((size_t)ab * ADIM + ach * 32) * TIN;
                float s[8];
                #pragma unroll
                for (int a8 = 0; a8 < 8; a8++) {
                    int al = ah * 8 + a8;
                    s[a8] = sc->qp[al] + __ldg(kb + al * TIN + ti) + sc->ldbs[al];
                }
                #pragma unroll 4
                for (int f = 0; f < NFLT; f++) {
                    float lf = sc->loc[ti][f];
                    #pragma unroll
                    for (int a8 = 0; a8 < 8; a8++)
                        s[a8] += lf * sc->ldws[f * 32 + ah * 8 + a8];
                }
                float e = 0.f;
                #pragma unroll
                for (int a8 = 0; a8 < 8; a8++) {
                    float u = __expf(-2.f * fabsf(s[a8]));
                    float th = __fdividef(1.f - u, 1.f + u);
                    e += copysignf(th, s[a8]) * sc->vws[ah * 8 + a8];
                }
                sc->es[ah][ti] = e;
            }
            __syncthreads();
            if (tid < 256)
                __stcg(&g_epart[(ach * BN + ab) * TIN + tid],
                       sc->es[0][tid] + sc->es[1][tid] + sc->es[2][tid] + sc->es[3][tid]);
        }
        grid_bar(++gen, j, tid);

        // ---- phase D: softmax + context (ctx written as fragments) ----
        {
            const int ec = ach;
            float ev = 0.f, ex = 0.f;
            if (tid < 256) {
                ev = vb[0] + g_maskneg[ab * TIN + tid];
                #pragma unroll
                for (int ac = 0; ac < 4; ac++)
                    ev += __ldcg(&g_epart[(ac * BN + ab) * TIN + tid]);
                sd->red[tid] = ev;
            }
            __syncthreads();
            for (int s = 128; s > 0; s >>= 1) {
                if (tid < s) sd->red[tid] = fmaxf(sd->red[tid], sd->red[tid + s]);
                __syncthreads();
            }
            float mx = sd->red[0];
            __syncthreads();
            if (tid < 256) { ex = expf(ev - mx); sd->red[tid] = ex; }
            __syncthreads();
            for (int s = 128; s > 0; s >>= 1) {
                if (tid < s) sd->red[tid] += sd->red[tid + s];
                __syncthreads();
            }
            float inv = 1.f / sd->red[0];
            __syncthreads();
            if (tid < 256) {
                float w = ex * inv;
                sd->ws[tid] = w;
                if (ec == 0) {
                    __stcg(&g_wcum[ab * TIN + tid],
                           __ldcg(&g_wcum[ab * TIN + tid]) + w);
                    out_align[((size_t)ab * TOUT + t) * TIN + tid] = w;
                }
            }
            __syncthreads();
            {   // context: 128 cols x 8 t-slices
                int cl = tid & 127, q = tid >> 7;
                float acc = 0.f;
                #pragma unroll 4
                for (int tt = q * 32; tt < q * 32 + 32; tt++)
                    acc += sd->ws[tt] *
                           memory[((size_t)ab * TIN + tt) * EDIM + ec * 128 + cl];
                sd->cred[q][cl] = acc;
                __syncthreads();
                if (tid < 128) {
                    float cv = 0.f;
                    #pragma unroll
                    for (int q2 = 0; q2 < 8; q2++) cv += sd->cred[q2][tid];
                    int e = ec * 128 + tid;
                    frag_store(g_cxh[wb], g_cxl[wb], ab, e >> 8, e & 255, cv);
                    g_ctxall[((size_t)t * BN + ab) * EDIM + e] = cv;
                }
            }
        }
        grid_bar(++gen, j, tid);
    }
}

// ---------------- prenet: writes fragment buffers (+ mask in block 0) -------
__global__ void prenet_kernel(const float* __restrict__ targets,
                              const float* __restrict__ w1, const float* __restrict__ b1,
                              const float* __restrict__ w2, const float* __restrict__ b2,
                              const unsigned char* __restrict__ mask) {
    int bid = blockIdx.x;
    int t = bid >> 5, b = bid & 31;
    __shared__ float xin[NMEL];
    __shared__ float h[PRE];
    __shared__ int s_has;
    int tid = threadIdx.x;
    if (tid < NMEL) xin[tid] = (t == 0) ? 0.f : targets[(b * TOUT + (t - 1)) * NMEL + tid];
    __syncthreads();
    float acc = b1[tid];
    #pragma unroll 8
    for (int k = 0; k < NMEL; k++) acc += xin[k] * w1[k * PRE + tid];
    h[tid] = fmaxf(acc, 0.f);
    __syncthreads();
    float acc2 = b2[tid];
    #pragma unroll 8
    for (int k = 0; k < PRE; k++) acc2 += h[k] * w2[k * PRE + tid];
    frag_store(g_pnh + (size_t)t * 4096, g_pnl + (size_t)t * 4096,
               b, 0, tid, fmaxf(acc2, 0.f));

    if (bid == 0) {
        if (tid == 0) s_has = 0;
        __syncthreads();
        int local = 0;
        for (int i = tid; i < BN * TIN; i += 256)
            if ((i & 3) != 0 && mask[i] != 0) local = 1;
        if (local) atomicOr(&s_has, 1);
        __syncthreads();
        bool is_u8 = (s_has != 0);
        const int* mi = (const int*)mask;
        for (int i = tid; i < BN * TIN; i += 256) {
            int v = is_u8 ? (int)mask[i] : mi[i];
            g_maskneg[i] = v ? 0.f : -1e9f;
        }
    }
}

// ---------------- keys projection ----------------
__global__ void keys_kernel(const float* __restrict__ memory,
                            const float* __restrict__ mw, const float* __restrict__ mb) {
    int bid = blockIdx.x;
    int b = bid >> 8, t = bid & 255;
    __shared__ float x[EDIM];
    int tid = threadIdx.x;
    for (int i = tid; i < EDIM; i += 128) x[i] = memory[(b * TIN + t) * EDIM + i];
    __syncthreads();
    float acc = mb[tid];
    #pragma unroll 8
    for (int k = 0; k < EDIM; k++) acc += x[k] * mw[k * ADIM + tid];
    g_keysT[(b * ADIM + tid) * TIN + t] = acc;
}

// ---------------- output projections ----------------
__global__ void proj_kernel(const float* __restrict__ pw, const float* __restrict__ pb,
                            const float* __restrict__ gw, const float* __restrict__ gb,
                            float* __restrict__ out_mel, float* __restrict__ out_gate) {
    int bid = blockIdx.x;
    int t = bid >> 5, b = bid & 31;
    __shared__ float xo[DDIM + EDIM];
    int tid = threadIdx.x;
    for (int i = tid; i < DDIM; i += 128) xo[i] = g_h1all[(size_t)(t * BN + b) * DDIM + i];
    for (int i = tid; i < EDIM; i += 128) xo[DDIM + i] = g_ctxall[(size_t)(t * BN + b) * EDIM + i];
    __syncthreads();
    if (tid < NMEL) {
        float acc = pb[tid];
        #pragma unroll 8
        for (int k = 0; k < DDIM + EDIM; k++) acc += xo[k] * pw[k * NMEL + tid];
        out_mel[(size_t)(b * TOUT + t) * NMEL + tid] = acc;
    } else if (tid == NMEL) {
        float acc = gb[0];
        for (int k = 0; k < DDIM + EDIM; k++) acc += xo[k] * gw[k];
        out_gate[b * TOUT + t] = acc;
    }
}

// ---------------- launcher ----------------
extern "C" void kernel_launch(void* const* d_in, const int* in_sizes, int n_in,
                              void* d_out, int out_size) {
    (void)in_sizes; (void)n_in; (void)out_size;
    const float* memory  = (const float*)d_in[0];
    const float* targets = (const float*)d_in[1];
    const unsigned char* mask = (const unsigned char*)d_in[2];
    const float* p1w = (const float*)d_in[3];
    const float* p1b = (const float*)d_in[4];
    const float* p2w = (const float*)d_in[5];
    const float* p2b = (const float*)d_in[6];
    const float* l0k = (const float*)d_in[7];
    const float* l0r = (const float*)d_in[8];
    const float* l0b = (const float*)d_in[9];
    const float* l1k = (const float*)d_in[10];
    const float* l1r = (const float*)d_in[11];
    const float* l1b = (const float*)d_in[12];
    const float* qw  = (const float*)d_in[13];
    const float* qb  = (const float*)d_in[14];
    const float* mw  = (const float*)d_in[15];
    const float* mb  = (const float*)d_in[16];
    const float* vw  = (const float*)d_in[17];
    const float* vb  = (const float*)d_in[18];
    const float* ccw = (const float*)d_in[19];
    const float* ccb = (const float*)d_in[20];
    const float* ldw = (const float*)d_in[21];
    const float* ldb = (const float*)d_in[22];
    const float* pw  = (const float*)d_in[23];
    const float* pb  = (const float*)d_in[24];
    const float* gw  = (const float*)d_in[25];
    const float* gb  = (const float*)d_in[26];

    float* out       = (float*)d_out;
    float* out_mel   = out;
    float* out_gate  = out + (size_t)BN * TOUT * NMEL;
    float* out_align = out_gate + (size_t)BN * TOUT;

    static int smem_set = 0;
    if (!smem_set) {
        cudaFuncSetAttribute(decoder_persist,
                             cudaFuncAttributeMaxDynamicSharedMemorySize, DSMEM_BYTES);
        smem_set = 1;
    }

    uint4* pb0;
    uint4* pb1;
    cudaGetSymbolAddress((void**)&pb0, g_pb0);
    cudaGetSymbolAddress((void**)&pb1, g_pb1);

    pack_all_kernel<<<(KST0 + KST1) * 32, 256>>>(l0k, l0r, l1k, l1r, pb0, pb1);
    prenet_kernel<<<TOUT * BN, 256>>>(targets, p1w, p1b, p2w, p2b, mask);
    keys_kernel<<<BN * TIN, 128>>>(memory, mw, mb);
    decoder_persist<<<NCTA, NTHR, DSMEM_BYTES>>>(memory, l0b, l1b, qw, qb, vw, vb,
                                                 ccw, ccb, ldw, ldb, out_align);
    proj_kernel<<<TOUT * BN, 128>>>(pw, pb, gw, gb, out_mel, out_gate);
}

// round 14
// speedup vs baseline: 2.7279x; 1.6108x over previous
#include <cuda_runtime.h>
#include <cuda_bf16.h>
#include <math.h>
#include <string.h>

#define BN 32
#define TIN 256
#define TOUT 400
#define EDIM 512
#define ADIM 128
#define NFLT 32
#define KSZ 31
#define PRE 256
#define DDIM 1024
#define NMEL 80
#define ZN 4096
#define NCTA 128
#define NTHR 1024
#define KST0 112
#define KST1 160

// dynamic smem layout: B 3x32K, xh 3x16K, xl 3x16K; zf (8 slabs x 4K) aliases B
#define OFF_BB 0
#define OFF_XH 98304
#define OFF_XL 147456
#define DSMEM_BYTES 196608

// ---------------- persistent device scratch ----------------
__device__ float g_keysT[BN * ADIM * TIN];
__device__ float g_maskneg[BN * TIN];
__device__ float g_h1[2][BN * DDIM];
__device__ float g_wcum[BN * TIN];
__device__ float g_epart[4 * BN * TIN];
__device__ float g_h1all[TOUT * BN * DDIM];
__device__ float g_ctxall[TOUT * BN * EDIM];
__device__ unsigned g_flags[NCTA * 32];
__device__ unsigned g_relv[NCTA * 32];
// x operands resident as bf16 hi/lo MMA fragments (uint-packed pairs)
__device__ unsigned g_pnh[(size_t)TOUT * 4096], g_pnl[(size_t)TOUT * 4096];
__device__ unsigned g_h0h[2][4 * 4096], g_h0l[2][4 * 4096];
__device__ unsigned g_cxh[2][2 * 4096], g_cxl[2][2 * 4096];
__device__ unsigned g_h1h[2][4 * 4096], g_h1l[2][4 * 4096];
__device__ uint4 g_pb0[(size_t)NCTA * KST0 * 4 * 32];
__device__ uint4 g_pb1[(size_t)NCTA * KST1 * 4 * 32];

__device__ __forceinline__ float sigmoidf_(float x) { return 1.f / (1.f + expf(-x)); }

__device__ __forceinline__ unsigned smem_u32(const void* p) {
    unsigned a;
    asm("{ .reg .u64 t; cvta.to.shared.u64 t, %1; cvt.u32.u64 %0, t; }"
        : "=r"(a) : "l"(p));
    return a;
}
__device__ __forceinline__ void cpasync16(unsigned dst, const void* src) {
    asm volatile("cp.async.cg.shared.global [%0], [%1], 16;" :: "r"(dst), "l"(src));
}
#define CP_COMMIT() asm volatile("cp.async.commit_group;" ::: "memory")
#define CP_WAITG(n) asm volatile("cp.async.wait_group %0;" :: "n"(n) : "memory")

__device__ __forceinline__ unsigned pk2(__nv_bfloat16 a, __nv_bfloat16 b) {
    __nv_bfloat162 t(a, b);
    unsigned r;
    memcpy(&r, &t, 4);
    return r;
}
__device__ __forceinline__ void mma16816(float* d, unsigned a0, unsigned a1,
                                         unsigned a2, unsigned a3,
                                         unsigned b0, unsigned b1) {
    asm volatile("mma.sync.aligned.m16n8k16.row.col.f32.bf16.bf16.f32 "
                 "{%0,%1,%2,%3}, {%4,%5,%6,%7}, {%8,%9}, {%0,%1,%2,%3};"
                 : "+f"(d[0]), "+f"(d[1]), "+f"(d[2]), "+f"(d[3])
                 : "r"(a0), "r"(a1), "r"(a2), "r"(a3), "r"(b0), "r"(b1));
}

// fragment store: one fp32 value -> hi/lo bf16 at its MMA-fragment position.
__device__ __forceinline__ void frag_store(unsigned* bh, unsigned* bl,
                                           int row, int c, int kk, float v) {
    int rl = row & 15;
    int mi = row >> 4, t4 = rl & 7, rbit = rl >> 3;
    int k2 = kk >> 1, half = kk & 1;
    int ksg = k2 >> 3, p8 = k2 & 7, q = p8 & 3, kh = p8 >> 2;
    int uidx = c * 4096 + mi * 2048 + ksg * 128 + (t4 * 4 + q) * 4 + rbit + 2 * kh;
    __nv_bfloat16 hi = __float2bfloat16_rn(v);
    __nv_bfloat16 lo = __float2bfloat16_rn(v - __bfloat162float(hi));
    ((__nv_bfloat16*)(bh + uidx))[half] = hi;
    ((__nv_bfloat16*)(bl + uidx))[half] = lo;
}

// ---------------- contention-free grid barrier ----------------
__device__ __forceinline__ void grid_bar(unsigned gen, int j, int tid) {
    __syncthreads();
    if (j == 0) {
        if (tid >= 1 && tid < NCTA) {
            unsigned v;
            do {
                asm volatile("ld.acquire.gpu.u32 %0, [%1];"
                             : "=r"(v) : "l"(&g_flags[tid * 32]));
            } while (v != gen);
        }
        __syncthreads();
        if (tid == 0) asm volatile("fence.acq_rel.gpu;" ::: "memory");
        __syncthreads();
        if (tid < NCTA)
            asm volatile("st.release.gpu.u32 [%0], %1;"
                         :: "l"(&g_relv[tid * 32]), "r"(gen) : "memory");
    } else {
        if (tid == 0) {
            asm volatile("fence.acq_rel.gpu;" ::: "memory");
            asm volatile("st.release.gpu.u32 [%0], %1;"
                         :: "l"(&g_flags[j * 32]), "r"(gen) : "memory");
            unsigned v;
            do {
                asm volatile("ld.acquire.gpu.u32 %0, [%1];"
                             : "=r"(v) : "l"(&g_relv[j * 32]));
            } while (v != gen);
        }
        __syncthreads();
    }
}

// ---------------- attention smem structs (alias GEMM region) ------------
struct AttC {
    float h1s[DDIM];
    float wp[TIN + KSZ];
    float cws[KSZ * NFLT];
    float cbs[NFLT];
    float ldws[NFLT * 32];
    float ldbs[32], vws[32];
    float qred[32][32];
    float qp[32];
    float es[4][TIN];
    float loc[TIN][NFLT + 1];
};
struct AttD { float red[8]; float ws[256]; float cred[8][128]; };

// ---------------- combined weight pack ----------------
__device__ void pack_tile(const float* __restrict__ wK, const float* __restrict__ wR,
                          int KST, int KB1, uint4* __restrict__ out,
                          int ks, int nb, float (*w)[128]) {
    int k0 = ks * 16;
    const float* W = (k0 < KB1) ? wK + (size_t)k0 * ZN : wR + (size_t)(k0 - KB1) * ZN;
    int N0 = nb * 128;
    for (int i = threadIdx.x; i < 2048; i += 256)
        w[i >> 7][i & 127] = W[(size_t)(i >> 7) * ZN + N0 + (i & 127)];
    __syncthreads();
    int g = N0 >> 10, jbase = (N0 & 1023) >> 3;
    for (int s = threadIdx.x; s < 512; s += 256) {
        int jl = s >> 5, lane = s & 31;
        int q = lane & 3, t4 = lane >> 2;
        int n = jl * 8 + t4;
        float v0 = w[2 * q][n], v1 = w[2 * q + 1][n];
        float v2 = w[2 * q + 8][n], v3 = w[2 * q + 9][n];
        __nv_bfloat16 h0 = __float2bfloat16_rn(v0), h1 = __float2bfloat16_rn(v1);
        __nv_bfloat16 h2 = __float2bfloat16_rn(v2), h3 = __float2bfloat16_rn(v3);
        unsigned bh0 = pk2(h0, h1), bh1 = pk2(h2, h3);
        unsigned bl0 = pk2(__float2bfloat16_rn(v0 - __bfloat162float(h0)),
                           __float2bfloat16_rn(v1 - __bfloat162float(h1)));
        unsigned bl1 = pk2(__float2bfloat16_rn(v2 - __bfloat162float(h2)),
                           __float2bfloat16_rn(v3 - __bfloat162float(h3)));
        int jj = jbase + jl;
        out[((size_t)(jj * KST + ks) * 4 + g) * 32 + lane] = make_uint4(bh0, bh1, bl0, bl1);
    }
}

__global__ void pack_all_kernel(const float* __restrict__ l0k, const float* __restrict__ l0r,
                                const float* __restrict__ l1k, const float* __restrict__ l1r,
                                uint4* __restrict__ o0, uint4* __restrict__ o1) {
    __shared__ float w[16][128];
    int bid = blockIdx.x;
    if (bid < KST0 * 32)
        pack_tile(l0k, l0r, KST0, 768, o0, bid % KST0, bid / KST0, w);
    else {
        bid -= KST0 * 32;
        pack_tile(l1k, l1r, KST1, 1536, o1, bid % KST1, bid / KST1, w);
    }
}

// ---------------- bf16 MMA GEMM: A reused across 4 g; zf = 8 k-slabs --------
template <int KTOT, int KST>
__device__ __forceinline__ void gemm_mma(char* dsm, int j, int tid,
                                         const unsigned* shA, const unsigned* slA, int nA,
                                         const unsigned* shB, const unsigned* slB, int nAB,
                                         const unsigned* shC, const unsigned* slC,
                                         const uint4* pB, float* zf) {
    constexpr int NC = KTOT / 256;
    uint4* Bb = (uint4*)(dsm + OFF_BB);
    float acc[4][4];
    #pragma unroll
    for (int g = 0; g < 4; g++)
        #pragma unroll
        for (int i = 0; i < 4; i++) acc[g][i] = 0.f;

    if (tid >= 512) {
        const int p = tid - 512;
        unsigned* xhU = (unsigned*)(dsm + OFF_XH);
        unsigned* xlU = (unsigned*)(dsm + OFF_XL);
        auto cpAll = [&](int c) {
            const unsigned *sh, *sl;
            if (c < nA)       { sh = shA + (size_t)c * 4096;         sl = slA + (size_t)c * 4096; }
            else if (c < nAB) { sh = shB + (size_t)(c - nA) * 4096;  sl = slB + (size_t)(c - nA) * 4096; }
            else              { sh = shC + (size_t)(c - nAB) * 4096; sl = slC + (size_t)(c - nAB) * 4096; }
            char* dxh = (char*)(xhU + (c % 3) * 4096);
            char* dxl = (char*)(xlU + (c % 3) * 4096);
            char* dB  = (char*)(Bb + (size_t)(c % 3) * 2048);
            const char* srcB = (const char*)(pB + (size_t)(j * KST + c * 16) * 128);
            cpasync16(smem_u32(dxh + p * 16), (const char*)sh + p * 16);
            cpasync16(smem_u32(dxh + (p + 512) * 16), (const char*)sh + (p + 512) * 16);
            cpasync16(smem_u32(dxl + p * 16), (const char*)sl + p * 16);
            cpasync16(smem_u32(dxl + (p + 512) * 16), (const char*)sl + (p + 512) * 16);
            #pragma unroll
            for (int i = 0; i < 4; i++)
                cpasync16(smem_u32(dB + (p + 512 * i) * 16), srcB + (p + 512 * i) * 16);
            CP_COMMIT();
        };
        cpAll(0); cpAll(1);
        for (int c = 0; c < NC; c++) {
            if (c < NC - 1) CP_WAITG(1); else CP_WAITG(0);
            __syncthreads();
            if (c + 2 < NC) cpAll(c + 2);
        }
    } else {
        // consumers: warp = (mi, ksg-pair kp), all 4 g per A-load
        const int w = tid >> 5, lane = tid & 31;
        const int mi = w & 1, kp = w >> 1;           // kp 0..7
        const uint4* xh4 = (const uint4*)(dsm + OFF_XH);
        const uint4* xl4 = (const uint4*)(dsm + OFF_XL);
        for (int c = 0; c < NC; c++) {
            __syncthreads();
            const uint4* Bw = Bb + (c % 3) * 2048 + lane;
            const uint4* xhb = xh4 + (c % 3) * 1024 + mi * 512 + lane;
            const uint4* xlb = xl4 + (c % 3) * 1024 + mi * 512 + lane;
            #pragma unroll
            for (int k2 = 0; k2 < 2; k2++) {
                int ksg = kp * 2 + k2;
                uint4 A = xhb[ksg * 32];
                uint4 L = xlb[ksg * 32];
                #pragma unroll
                for (int g = 0; g < 4; g++) {
                    uint4 B = Bw[ksg * 128 + g * 32];
                    mma16816(acc[g], A.x, A.y, A.z, A.w, B.x, B.y);
                    mma16816(acc[g], L.x, L.y, L.z, L.w, B.x, B.y);
                    mma16816(acc[g], A.x, A.y, A.z, A.w, B.z, B.w);
                }
            }
        }
    }
    __syncthreads();   // all B buffers dead; zf region (aliased) now writable
    if (tid < 512) {
        const int w = tid >> 5, lane = tid & 31;
        const int mi = w & 1, kp = w >> 1;
        const int t4 = lane >> 2, q = lane & 3;
        const int r0 = mi * 16 + t4;
        float* zfp = zf + kp * 1024;
        #pragma unroll
        for (int g = 0; g < 4; g++) {
            zfp[r0 * 32 + g * 8 + 2 * q]           = acc[g][0];
            zfp[r0 * 32 + g * 8 + 2 * q + 1]       = acc[g][1];
            zfp[(r0 + 8) * 32 + g * 8 + 2 * q]     = acc[g][2];
            zfp[(r0 + 8) * 32 + g * 8 + 2 * q + 1] = acc[g][3];
        }
    }
    __syncthreads();
}

// ---------------- persistent decoder kernel ----------------
__global__ __launch_bounds__(NTHR, 1) void decoder_persist(
    const float* __restrict__ memory,
    const float* __restrict__ l0b, const float* __restrict__ l1b,
    const float* __restrict__ qw, const float* __restrict__ qb,
    const float* __restrict__ vw, const float* __restrict__ vb,
    const float* __restrict__ cw, const float* __restrict__ cb,
    const float* __restrict__ ldw, const float* __restrict__ ldb,
    float* __restrict__ out_align) {
    extern __shared__ char dsm[];
    float* zf = (float*)dsm;              // 8 slabs x 1024 floats (aliases B)
    AttC* sc = (AttC*)dsm;
    AttD* sd = (AttD*)dsm;
    const int j = blockIdx.x;
    const int tid = threadIdx.x;
    const int ab = j >> 2, ach = j & 3;

    unsigned gen;
    asm volatile("ld.acquire.gpu.u32 %0, [%1];" : "=r"(gen) : "l"(&g_relv[j * 32]));

    {   // init: zero parity-0 fragment buffers + wcum
        int i = j * NTHR + tid;
        if (i < 4 * 4096) {
            g_h0h[0][i] = 0u; g_h0l[0][i] = 0u;
            g_h1h[0][i] = 0u; g_h1l[0][i] = 0u;
        }
        if (i < 2 * 4096) { g_cxh[0][i] = 0u; g_cxl[0][i] = 0u; }
        if (i < BN * TIN) g_wcum[i] = 0.f;
    }

    float c0r = 0.f, c1r = 0.f;
    const int bq = tid >> 3, dd = tid & 7;
    const int du = 8 * j + dd;

    grid_bar(++gen, j, tid);

    for (int t = 0; t < TOUT; t++) {
        const int rb = t & 1, wb = (t + 1) & 1;

        // ---- phase A: LSTM0 GEMM + gates ----
        gemm_mma<1792, KST0>(dsm, j, tid,
                             g_pnh + (size_t)t * 4096, g_pnl + (size_t)t * 4096, 1,
                             g_cxh[rb], g_cxl[rb], 3,
                             g_h0h[rb], g_h0l[rb], g_pb0, zf);
        if (tid < 256) {
            float zi = l0b[du], zff = l0b[1024 + du];
            float zg = l0b[2048 + du], zo = l0b[3072 + du];
            #pragma unroll
            for (int s = 0; s < 8; s++) {
                const float* zp = zf + s * 1024 + bq * 32;
                zi += zp[dd]; zff += zp[8 + dd]; zg += zp[16 + dd]; zo += zp[24 + dd];
            }
            float ii = sigmoidf_(zi), ff = sigmoidf_(zff), oo = sigmoidf_(zo);
            c0r = ff * c0r + ii * tanhf(zg);
            frag_store(g_h0h[wb], g_h0l[wb], bq, du >> 8, du & 255, oo * tanhf(c0r));
        }
        grid_bar(++gen, j, tid);

        // ---- phase B: LSTM1 GEMM + gates ----
        gemm_mma<2560, KST1>(dsm, j, tid,
                             g_h0h[wb], g_h0l[wb], 4,
                             g_cxh[rb], g_cxl[rb], 6,
                             g_h1h[rb], g_h1l[rb], g_pb1, zf);
        if (tid < 256) {
            float zi = l1b[du], zff = l1b[1024 + du];
            float zg = l1b[2048 + du], zo = l1b[3072 + du];
            #pragma unroll
            for (int s = 0; s < 8; s++) {
                const float* zp = zf + s * 1024 + bq * 32;
                zi += zp[dd]; zff += zp[8 + dd]; zg += zp[16 + dd]; zo += zp[24 + dd];
            }
            float ii = sigmoidf_(zi), ff = sigmoidf_(zff), oo = sigmoidf_(zo);
            c1r = ff * c1r + ii * tanhf(zg);
            float h = oo * tanhf(c1r);
            frag_store(g_h1h[wb], g_h1l[wb], bq, du >> 8, du & 255, h);
            __stcg(&g_h1[wb][bq * DDIM + du], h);
            g_h1all[((size_t)t * BN + bq) * DDIM + du] = h;
        }
        grid_bar(++gen, j, tid);

        // ---- phase C: attention energies (CTA = b x a-chunk) ----
        {
            const float* h1cur = g_h1[wb];
            for (int i = tid; i < DDIM; i += NTHR)
                sc->h1s[i] = __ldcg(h1cur + ab * DDIM + i);
            for (int i = tid; i < TIN + KSZ - 1; i += NTHR) {
                int jj = i - (KSZ / 2);
                sc->wp[i] = (jj >= 0 && jj < TIN) ? __ldcg(&g_wcum[ab * TIN + jj]) : 0.f;
            }
            for (int i = tid; i < KSZ * NFLT; i += NTHR) sc->cws[i] = cw[i];
            if (tid < NFLT) sc->cbs[tid] = cb[tid];
            for (int i = tid; i < NFLT * 32; i += NTHR)
                sc->ldws[i] = ldw[(i >> 5) * ADIM + ach * 32 + (i & 31)];
            if (tid < 32) {
                sc->ldbs[tid] = ldb[ach * 32 + tid];
                sc->vws[tid]  = vw[ach * 32 + tid];
            }
            __syncthreads();
            {   // qp partials: 32 parts x 32 k
                int al = tid & 31, part = tid >> 5;
                float a0 = 0.f;
                int k0 = part * 32;
                #pragma unroll 8
                for (int k = k0; k < k0 + 32; k++)
                    a0 += sc->h1s[k] * qw[k * ADIM + ach * 32 + al];
                sc->qred[part][al] = a0;
            }
            {   // conv: thread (ti, fq) does 8 filters
                int ti = tid & 255, fq = tid >> 8;
                float lf[8];
                #pragma unroll
                for (int f = 0; f < 8; f++) lf[f] = sc->cbs[fq * 8 + f];
                for (int jk = 0; jk < KSZ; jk++) {
                    float w = sc->wp[ti + jk];
                    #pragma unroll
                    for (int f = 0; f < 8; f++)
                        lf[f] += w * sc->cws[jk * NFLT + fq * 8 + f];
                }
                #pragma unroll
                for (int f = 0; f < 8; f++) sc->loc[ti][fq * 8 + f] = lf[f];
            }
            __syncthreads();
            if (tid < 32) {
                float s = 0.f;
                #pragma unroll
                for (int p = 0; p < 32; p++) s += sc->qred[p][tid];
                sc->qp[tid] = s + qb[ach * 32 + tid];
            }
            __syncthreads();
            {   // energies: thread (ti, ah) does 8 a's; keys direct from L2
                int ti = tid & 255, ah = tid >> 8;
                const float* kb = g_keysT + ((size_t)ab * ADIM + ach * 32) * TIN;
                float s[8];
                #pragma unroll
                for (int a8 = 0; a8 < 8; a8++) {
                    int al = ah * 8 + a8;
                    s[a8] = sc->qp[al] + __ldg(kb + al * TIN + ti) + sc->ldbs[al];
                }
                #pragma unroll 4
                for (int f = 0; f < NFLT; f++) {
                    float lf = sc->loc[ti][f];
                    #pragma unroll
                    for (int a8 = 0; a8 < 8; a8++)
                        s[a8] += lf * sc->ldws[f * 32 + ah * 8 + a8];
                }
                float e = 0.f;
                #pragma unroll
                for (int a8 = 0; a8 < 8; a8++) {
                    float u = __expf(-2.f * fabsf(s[a8]));
                    float th = __fdividef(1.f - u, 1.f + u);
                    e += copysignf(th, s[a8]) * sc->vws[ah * 8 + a8];
                }
                sc->es[ah][ti] = e;
            }
            __syncthreads();
            if (tid < 256)
                __stcg(&g_epart[(ach * BN + ab) * TIN + tid],
                       sc->es[0][tid] + sc->es[1][tid] + sc->es[2][tid] + sc->es[3][tid]);
        }
        grid_bar(++gen, j, tid);

        // ---- phase D: softmax (no max pass; energies bounded) + context ----
        {
            const int ec = ach;
            float ex = 0.f;
            if (tid < 256) {
                float ev = vb[0] + g_maskneg[ab * TIN + tid];
                #pragma unroll
                for (int ac = 0; ac < 4; ac++)
                    ev += __ldcg(&g_epart[(ac * BN + ab) * TIN + tid]);
                ex = expf(ev);
            }
            float s = ex;
            #pragma unroll
            for (int o = 16; o > 0; o >>= 1) s += __shfl_xor_sync(0xffffffffu, s, o);
            if (tid < 256 && (tid & 31) == 0) sd->red[tid >> 5] = s;
            __syncthreads();
            float tot = 0.f;
            #pragma unroll
            for (int i = 0; i < 8; i++) tot += sd->red[i];
            float inv = 1.f / tot;
            if (tid < 256) {
                float w = ex * inv;
                sd->ws[tid] = w;
                if (ec == 0) {
                    __stcg(&g_wcum[ab * TIN + tid],
                           __ldcg(&g_wcum[ab * TIN + tid]) + w);
                    out_align[((size_t)ab * TOUT + t) * TIN + tid] = w;
                }
            }
            __syncthreads();
            {   // context: 128 cols x 8 t-slices
                int cl = tid & 127, q = tid >> 7;
                float acc = 0.f;
                #pragma unroll 4
                for (int tt = q * 32; tt < q * 32 + 32; tt++)
                    acc += sd->ws[tt] *
                           memory[((size_t)ab * TIN + tt) * EDIM + ec * 128 + cl];
                sd->cred[q][cl] = acc;
                __syncthreads();
                if (tid < 128) {
                    float cv = 0.f;
                    #pragma unroll
                    for (int q2 = 0; q2 < 8; q2++) cv += sd->cred[q2][tid];
                    int e = ec * 128 + tid;
                    frag_store(g_cxh[wb], g_cxl[wb], ab, e >> 8, e & 255, cv);
                    g_ctxall[((size_t)t * BN + ab) * EDIM + e] = cv;
                }
            }
        }
        grid_bar(++gen, j, tid);
    }
}

// ---------------- prenet: writes fragment buffers (+ mask in block 0) -------
__global__ void prenet_kernel(const float* __restrict__ targets,
                              const float* __restrict__ w1, const float* __restrict__ b1,
                              const float* __restrict__ w2, const float* __restrict__ b2,
                              const unsigned char* __restrict__ mask) {
    int bid = blockIdx.x;
    int t = bid >> 5, b = bid & 31;
    __shared__ float xin[NMEL];
    __shared__ float h[PRE];
    __shared__ int s_has;
    int tid = threadIdx.x;
    if (tid < NMEL) xin[tid] = (t == 0) ? 0.f : targets[(b * TOUT + (t - 1)) * NMEL + tid];
    __syncthreads();
    float acc = b1[tid];
    #pragma unroll 8
    for (int k = 0; k < NMEL; k++) acc += xin[k] * w1[k * PRE + tid];
    h[tid] = fmaxf(acc, 0.f);
    __syncthreads();
    float acc2 = b2[tid];
    #pragma unroll 8
    for (int k = 0; k < PRE; k++) acc2 += h[k] * w2[k * PRE + tid];
    frag_store(g_pnh + (size_t)t * 4096, g_pnl + (size_t)t * 4096,
               b, 0, tid, fmaxf(acc2, 0.f));

    if (bid == 0) {
        if (tid == 0) s_has = 0;
        __syncthreads();
        int local = 0;
        for (int i = tid; i < BN * TIN; i += 256)
            if ((i & 3) != 0 && mask[i] != 0) local = 1;
        if (local) atomicOr(&s_has, 1);
        __syncthreads();
        bool is_u8 = (s_has != 0);
        const int* mi = (const int*)mask;
        for (int i = tid; i < BN * TIN; i += 256) {
            int v = is_u8 ? (int)mask[i] : mi[i];
            g_maskneg[i] = v ? 0.f : -1e9f;
        }
    }
}

// ---------------- keys projection ----------------
__global__ void keys_kernel(const float* __restrict__ memory,
                            const float* __restrict__ mw, const float* __restrict__ mb) {
    int bid = blockIdx.x;
    int b = bid >> 8, t = bid & 255;
    __shared__ float x[EDIM];
    int tid = threadIdx.x;
    for (int i = tid; i < EDIM; i += 128) x[i] = memory[(b * TIN + t) * EDIM + i];
    __syncthreads();
    float acc = mb[tid];
    #pragma unroll 8
    for (int k = 0; k < EDIM; k++) acc += x[k] * mw[k * ADIM + tid];
    g_keysT[(b * ADIM + tid) * TIN + t] = acc;
}

// ---------------- output projections ----------------
__global__ void proj_kernel(const float* __restrict__ pw, const float* __restrict__ pb,
                            const float* __restrict__ gw, const float* __restrict__ gb,
                            float* __restrict__ out_mel, float* __restrict__ out_gate) {
    int bid = blockIdx.x;
    int t = bid >> 5, b = bid & 31;
    __shared__ float xo[DDIM + EDIM];
    int tid = threadIdx.x;
    for (int i = tid; i < DDIM; i += 128) xo[i] = g_h1all[(size_t)(t * BN + b) * DDIM + i];
    for (int i = tid; i < EDIM; i += 128) xo[DDIM + i] = g_ctxall[(size_t)(t * BN + b) * EDIM + i];
    __syncthreads();
    if (tid < NMEL) {
        float acc = pb[tid];
        #pragma unroll 8
        for (int k = 0; k < DDIM + EDIM; k++) acc += xo[k] * pw[k * NMEL + tid];
        out_mel[(size_t)(b * TOUT + t) * NMEL + tid] = acc;
    } else if (tid == NMEL) {
        float acc = gb[0];
        for (int k = 0; k < DDIM + EDIM; k++) acc += xo[k] * gw[k];
        out_gate[b * TOUT + t] = acc;
    }
}

// ---------------- launcher ----------------
extern "C" void kernel_launch(void* const* d_in, const int* in_sizes, int n_in,
                              void* d_out, int out_size) {
    (void)in_sizes; (void)n_in; (void)out_size;
    const float* memory  = (const float*)d_in[0];
    const float* targets = (const float*)d_in[1];
    const unsigned char* mask = (const unsigned char*)d_in[2];
    const float* p1w = (const float*)d_in[3];
    const float* p1b = (const float*)d_in[4];
    const float* p2w = (const float*)d_in[5];
    const float* p2b = (const float*)d_in[6];
    const float* l0k = (const float*)d_in[7];
    const float* l0r = (const float*)d_in[8];
    const float* l0b = (const float*)d_in[9];
    const float* l1k = (const float*)d_in[10];
    const float* l1r = (const float*)d_in[11];
    const float* l1b = (const float*)d_in[12];
    const float* qw  = (const float*)d_in[13];
    const float* qb  = (const float*)d_in[14];
    const float* mw  = (const float*)d_in[15];
    const float* mb  = (const float*)d_in[16];
    const float* vw  = (const float*)d_in[17];
    const float* vb  = (const float*)d_in[18];
    const float* ccw = (const float*)d_in[19];
    const float* ccb = (const float*)d_in[20];
    const float* ldw = (const float*)d_in[21];
    const float* ldb = (const float*)d_in[22];
    const float* pw  = (const float*)d_in[23];
    const float* pb  = (const float*)d_in[24];
    const float* gw  = (const float*)d_in[25];
    const float* gb  = (const float*)d_in[26];

    float* out       = (float*)d_out;
    float* out_mel   = out;
    float* out_gate  = out + (size_t)BN * TOUT * NMEL;
    float* out_align = out_gate + (size_t)BN * TOUT;

    static int smem_set = 0;
    if (!smem_set) {
        cudaFuncSetAttribute(decoder_persist,
                             cudaFuncAttributeMaxDynamicSharedMemorySize, DSMEM_BYTES);
        smem_set = 1;
    }

    uint4* pb0;
    uint4* pb1;
    cudaGetSymbolAddress((void**)&pb0, g_pb0);
    cudaGetSymbolAddress((void**)&pb1, g_pb1);

    pack_all_kernel<<<(KST0 + KST1) * 32, 256>>>(l0k, l0r, l1k, l1r, pb0, pb1);
    prenet_kernel<<<TOUT * BN, 256>>>(targets, p1w, p1b, p2w, p2b, mask);
    keys_kernel<<<BN * TIN, 128>>>(memory, mw, mb);
    decoder_persist<<<NCTA, NTHR, DSMEM_BYTES>>>(memory, l0b, l1b, qw, qb, vw, vb,
                                                 ccw, ccb, ldw, ldb, out_align);
    proj_kernel<<<TOUT * BN, 128>>>(pw, pb, gw, gb, out_mel, out_gate);
}

// round 15
// speedup vs baseline: 2.7959x; 1.0249x over previous
#include <cuda_runtime.h>
#include <cuda_bf16.h>
#include <math.h>
#include <string.h>

#define BN 32
#define TIN 256
#define TOUT 400
#define EDIM 512
#define ADIM 128
#define NFLT 32
#define KSZ 31
#define PRE 256
#define DDIM 1024
#define NMEL 80
#define ZN 4096
#define NCTA 128
#define NTHR 1024
#define KST0 112
#define KST1 160

// dynamic smem layout: B 3x32K, xh 3x16K, xl 3x16K; zf (8 slabs x 4K) aliases B
#define OFF_BB 0
#define OFF_XH 98304
#define OFF_XL 147456
#define DSMEM_BYTES 196608

// ---------------- persistent device scratch ----------------
__device__ float g_keysT[BN * ADIM * TIN];
__device__ float g_maskneg[BN * TIN];
__device__ float g_h1[2][BN * DDIM];
__device__ float g_wcum[BN * TIN];
__device__ float g_epart[4 * BN * TIN];
__device__ float g_h1all[TOUT * BN * DDIM];
__device__ float g_ctxall[TOUT * BN * EDIM];
__device__ unsigned g_flags[NCTA * 32];
__device__ unsigned g_relv[NCTA * 32];
// x operands resident as bf16 hi/lo MMA fragments (uint-packed pairs)
__device__ unsigned g_pnh[(size_t)TOUT * 4096], g_pnl[(size_t)TOUT * 4096];
__device__ unsigned g_h0h[2][4 * 4096], g_h0l[2][4 * 4096];
__device__ unsigned g_cxh[2][2 * 4096], g_cxl[2][2 * 4096];
__device__ unsigned g_h1h[2][4 * 4096], g_h1l[2][4 * 4096];
__device__ uint4 g_pb0[(size_t)NCTA * KST0 * 4 * 32];
__device__ uint4 g_pb1[(size_t)NCTA * KST1 * 4 * 32];

__device__ __forceinline__ float sigmoidf_(float x) { return 1.f / (1.f + expf(-x)); }

__device__ __forceinline__ unsigned smem_u32(const void* p) {
    unsigned a;
    asm("{ .reg .u64 t; cvta.to.shared.u64 t, %1; cvt.u32.u64 %0, t; }"
        : "=r"(a) : "l"(p));
    return a;
}
__device__ __forceinline__ void cpasync16(unsigned dst, const void* src) {
    asm volatile("cp.async.cg.shared.global [%0], [%1], 16;" :: "r"(dst), "l"(src));
}
#define CP_COMMIT() asm volatile("cp.async.commit_group;" ::: "memory")
#define CP_WAITG(n) asm volatile("cp.async.wait_group %0;" :: "n"(n) : "memory")

__device__ __forceinline__ unsigned pk2(__nv_bfloat16 a, __nv_bfloat16 b) {
    __nv_bfloat162 t(a, b);
    unsigned r;
    memcpy(&r, &t, 4);
    return r;
}
__device__ __forceinline__ void mma16816(float* d, unsigned a0, unsigned a1,
                                         unsigned a2, unsigned a3,
                                         unsigned b0, unsigned b1) {
    asm volatile("mma.sync.aligned.m16n8k16.row.col.f32.bf16.bf16.f32 "
                 "{%0,%1,%2,%3}, {%4,%5,%6,%7}, {%8,%9}, {%0,%1,%2,%3};"
                 : "+f"(d[0]), "+f"(d[1]), "+f"(d[2]), "+f"(d[3])
                 : "r"(a0), "r"(a1), "r"(a2), "r"(a3), "r"(b0), "r"(b1));
}

// fragment store: one fp32 value -> hi/lo bf16 at its MMA-fragment position.
__device__ __forceinline__ void frag_store(unsigned* bh, unsigned* bl,
                                           int row, int c, int kk, float v) {
    int rl = row & 15;
    int mi = row >> 4, t4 = rl & 7, rbit = rl >> 3;
    int k2 = kk >> 1, half = kk & 1;
    int ksg = k2 >> 3, p8 = k2 & 7, q = p8 & 3, kh = p8 >> 2;
    int uidx = c * 4096 + mi * 2048 + ksg * 128 + (t4 * 4 + q) * 4 + rbit + 2 * kh;
    __nv_bfloat16 hi = __float2bfloat16_rn(v);
    __nv_bfloat16 lo = __float2bfloat16_rn(v - __bfloat162float(hi));
    ((__nv_bfloat16*)(bh + uidx))[half] = hi;
    ((__nv_bfloat16*)(bl + uidx))[half] = lo;
}

// ---------------- contention-free grid barrier ----------------
__device__ __forceinline__ void grid_bar(unsigned gen, int j, int tid) {
    __syncthreads();
    if (j == 0) {
        if (tid >= 1 && tid < NCTA) {
            unsigned v;
            do {
                asm volatile("ld.acquire.gpu.u32 %0, [%1];"
                             : "=r"(v) : "l"(&g_flags[tid * 32]));
            } while (v != gen);
        }
        __syncthreads();
        if (tid == 0) asm volatile("fence.acq_rel.gpu;" ::: "memory");
        __syncthreads();
        if (tid < NCTA)
            asm volatile("st.release.gpu.u32 [%0], %1;"
                         :: "l"(&g_relv[tid * 32]), "r"(gen) : "memory");
    } else {
        if (tid == 0) {
            asm volatile("fence.acq_rel.gpu;" ::: "memory");
            asm volatile("st.release.gpu.u32 [%0], %1;"
                         :: "l"(&g_flags[j * 32]), "r"(gen) : "memory");
            unsigned v;
            do {
                asm volatile("ld.acquire.gpu.u32 %0, [%1];"
                             : "=r"(v) : "l"(&g_relv[j * 32]));
            } while (v != gen);
        }
        __syncthreads();
    }
}

// ---------------- attention smem structs (alias GEMM region) ------------
struct AttC {
    float h1s[DDIM];
    float wp[TIN + KSZ];
    float cws[KSZ * NFLT];
    float cbs[NFLT];
    float ldws[NFLT * 32];
    float ldbs[32], vws[32];
    float qred[32][32];
    float qp[32];
    float es[4][TIN];
    float loc[TIN][NFLT + 1];
};
struct AttD { float red[8]; float ws[256]; float cred[8][128]; };

// ---------------- combined weight pack ----------------
__device__ void pack_tile(const float* __restrict__ wK, const float* __restrict__ wR,
                          int KST, int KB1, uint4* __restrict__ out,
                          int ks, int nb, float (*w)[128]) {
    int k0 = ks * 16;
    const float* W = (k0 < KB1) ? wK + (size_t)k0 * ZN : wR + (size_t)(k0 - KB1) * ZN;
    int N0 = nb * 128;
    for (int i = threadIdx.x; i < 2048; i += 256)
        w[i >> 7][i & 127] = W[(size_t)(i >> 7) * ZN + N0 + (i & 127)];
    __syncthreads();
    int g = N0 >> 10, jbase = (N0 & 1023) >> 3;
    for (int s = threadIdx.x; s < 512; s += 256) {
        int jl = s >> 5, lane = s & 31;
        int q = lane & 3, t4 = lane >> 2;
        int n = jl * 8 + t4;
        float v0 = w[2 * q][n], v1 = w[2 * q + 1][n];
        float v2 = w[2 * q + 8][n], v3 = w[2 * q + 9][n];
        __nv_bfloat16 h0 = __float2bfloat16_rn(v0), h1 = __float2bfloat16_rn(v1);
        __nv_bfloat16 h2 = __float2bfloat16_rn(v2), h3 = __float2bfloat16_rn(v3);
        unsigned bh0 = pk2(h0, h1), bh1 = pk2(h2, h3);
        unsigned bl0 = pk2(__float2bfloat16_rn(v0 - __bfloat162float(h0)),
                           __float2bfloat16_rn(v1 - __bfloat162float(h1)));
        unsigned bl1 = pk2(__float2bfloat16_rn(v2 - __bfloat162float(h2)),
                           __float2bfloat16_rn(v3 - __bfloat162float(h3)));
        int jj = jbase + jl;
        out[((size_t)(jj * KST + ks) * 4 + g) * 32 + lane] = make_uint4(bh0, bh1, bl0, bl1);
    }
}

__global__ void pack_all_kernel(const float* __restrict__ l0k, const float* __restrict__ l0r,
                                const float* __restrict__ l1k, const float* __restrict__ l1r,
                                uint4* __restrict__ o0, uint4* __restrict__ o1) {
    __shared__ float w[16][128];
    int bid = blockIdx.x;
    if (bid < KST0 * 32)
        pack_tile(l0k, l0r, KST0, 768, o0, bid % KST0, bid / KST0, w);
    else {
        bid -= KST0 * 32;
        pack_tile(l1k, l1r, KST1, 1536, o1, bid % KST1, bid / KST1, w);
    }
}

// ---------------- bf16 MMA GEMM: A reused across 4 g; zf = 8 k-slabs --------
template <int KTOT, int KST>
__device__ __forceinline__ void gemm_mma(char* dsm, int j, int tid,
                                         const unsigned* shA, const unsigned* slA, int nA,
                                         const unsigned* shB, const unsigned* slB, int nAB,
                                         const unsigned* shC, const unsigned* slC,
                                         const uint4* pB, float* zf) {
    constexpr int NC = KTOT / 256;
    uint4* Bb = (uint4*)(dsm + OFF_BB);
    float acc[4][4];
    #pragma unroll
    for (int g = 0; g < 4; g++)
        #pragma unroll
        for (int i = 0; i < 4; i++) acc[g][i] = 0.f;

    if (tid >= 512) {
        const int p = tid - 512;
        unsigned* xhU = (unsigned*)(dsm + OFF_XH);
        unsigned* xlU = (unsigned*)(dsm + OFF_XL);
        auto cpAll = [&](int c) {
            const unsigned *sh, *sl;
            if (c < nA)       { sh = shA + (size_t)c * 4096;         sl = slA + (size_t)c * 4096; }
            else if (c < nAB) { sh = shB + (size_t)(c - nA) * 4096;  sl = slB + (size_t)(c - nA) * 4096; }
            else              { sh = shC + (size_t)(c - nAB) * 4096; sl = slC + (size_t)(c - nAB) * 4096; }
            char* dxh = (char*)(xhU + (c % 3) * 4096);
            char* dxl = (char*)(xlU + (c % 3) * 4096);
            char* dB  = (char*)(Bb + (size_t)(c % 3) * 2048);
            const char* srcB = (const char*)(pB + (size_t)(j * KST + c * 16) * 128);
            cpasync16(smem_u32(dxh + p * 16), (const char*)sh + p * 16);
            cpasync16(smem_u32(dxh + (p + 512) * 16), (const char*)sh + (p + 512) * 16);
            cpasync16(smem_u32(dxl + p * 16), (const char*)sl + p * 16);
            cpasync16(smem_u32(dxl + (p + 512) * 16), (const char*)sl + (p + 512) * 16);
            #pragma unroll
            for (int i = 0; i < 4; i++)
                cpasync16(smem_u32(dB + (p + 512 * i) * 16), srcB + (p + 512 * i) * 16);
            CP_COMMIT();
        };
        cpAll(0); cpAll(1);
        for (int c = 0; c < NC; c++) {
            if (c < NC - 1) CP_WAITG(1); else CP_WAITG(0);
            __syncthreads();
            if (c + 2 < NC) cpAll(c + 2);
        }
    } else {
        // consumers: warp = (mi, ksg-pair kp), all 4 g per A-load
        const int w = tid >> 5, lane = tid & 31;
        const int mi = w & 1, kp = w >> 1;           // kp 0..7
        const uint4* xh4 = (const uint4*)(dsm + OFF_XH);
        const uint4* xl4 = (const uint4*)(dsm + OFF_XL);
        for (int c = 0; c < NC; c++) {
            __syncthreads();
            const uint4* Bw = Bb + (c % 3) * 2048 + lane;
            const uint4* xhb = xh4 + (c % 3) * 1024 + mi * 512 + lane;
            const uint4* xlb = xl4 + (c % 3) * 1024 + mi * 512 + lane;
            #pragma unroll
            for (int k2 = 0; k2 < 2; k2++) {
                int ksg = kp * 2 + k2;
                uint4 A = xhb[ksg * 32];
                uint4 L = xlb[ksg * 32];
                #pragma unroll
                for (int g = 0; g < 4; g++) {
                    uint4 B = Bw[ksg * 128 + g * 32];
                    mma16816(acc[g], A.x, A.y, A.z, A.w, B.x, B.y);
                    mma16816(acc[g], L.x, L.y, L.z, L.w, B.x, B.y);
                    mma16816(acc[g], A.x, A.y, A.z, A.w, B.z, B.w);
                }
            }
        }
    }
    __syncthreads();   // all B buffers dead; zf region (aliased) now writable
    if (tid < 512) {
        const int w = tid >> 5, lane = tid & 31;
        const int mi = w & 1, kp = w >> 1;
        const int t4 = lane >> 2, q = lane & 3;
        const int r0 = mi * 16 + t4;
        float* zfp = zf + kp * 1024;
        #pragma unroll
        for (int g = 0; g < 4; g++) {
            zfp[r0 * 32 + g * 8 + 2 * q]           = acc[g][0];
            zfp[r0 * 32 + g * 8 + 2 * q + 1]       = acc[g][1];
            zfp[(r0 + 8) * 32 + g * 8 + 2 * q]     = acc[g][2];
            zfp[(r0 + 8) * 32 + g * 8 + 2 * q + 1] = acc[g][3];
        }
    }
    __syncthreads();
}

// ---------------- persistent decoder kernel ----------------
__global__ __launch_bounds__(NTHR, 1) void decoder_persist(
    const float* __restrict__ memory,
    const float* __restrict__ l0b, const float* __restrict__ l1b,
    const float* __restrict__ qw, const float* __restrict__ qb,
    const float* __restrict__ vw, const float* __restrict__ vb,
    const float* __restrict__ cw, const float* __restrict__ cb,
    const float* __restrict__ ldw, const float* __restrict__ ldb,
    float* __restrict__ out_align) {
    extern __shared__ char dsm[];
    float* zf = (float*)dsm;              // 8 slabs x 1024 floats (aliases B)
    AttC* sc = (AttC*)dsm;
    AttD* sd = (AttD*)dsm;
    const int j = blockIdx.x;
    const int tid = threadIdx.x;
    const int ab = j >> 2, ach = j & 3;

    unsigned gen;
    asm volatile("ld.acquire.gpu.u32 %0, [%1];" : "=r"(gen) : "l"(&g_relv[j * 32]));

    {   // init: zero parity-0 fragment buffers + wcum
        int i = j * NTHR + tid;
        if (i < 4 * 4096) {
            g_h0h[0][i] = 0u; g_h0l[0][i] = 0u;
            g_h1h[0][i] = 0u; g_h1l[0][i] = 0u;
        }
        if (i < 2 * 4096) { g_cxh[0][i] = 0u; g_cxl[0][i] = 0u; }
        if (i < BN * TIN) g_wcum[i] = 0.f;
    }

    float c0r = 0.f, c1r = 0.f;
    const int bq = tid >> 3, dd = tid & 7;
    const int du = 8 * j + dd;

    grid_bar(++gen, j, tid);

    for (int t = 0; t < TOUT; t++) {
        const int rb = t & 1, wb = (t + 1) & 1;

        // ---- phase A: LSTM0 GEMM + gates ----
        gemm_mma<1792, KST0>(dsm, j, tid,
                             g_pnh + (size_t)t * 4096, g_pnl + (size_t)t * 4096, 1,
                             g_cxh[rb], g_cxl[rb], 3,
                             g_h0h[rb], g_h0l[rb], g_pb0, zf);
        if (tid < 256) {
            float zi = l0b[du], zff = l0b[1024 + du];
            float zg = l0b[2048 + du], zo = l0b[3072 + du];
            #pragma unroll
            for (int s = 0; s < 8; s++) {
                const float* zp = zf + s * 1024 + bq * 32;
                zi += zp[dd]; zff += zp[8 + dd]; zg += zp[16 + dd]; zo += zp[24 + dd];
            }
            float ii = sigmoidf_(zi), ff = sigmoidf_(zff), oo = sigmoidf_(zo);
            c0r = ff * c0r + ii * tanhf(zg);
            frag_store(g_h0h[wb], g_h0l[wb], bq, du >> 8, du & 255, oo * tanhf(c0r));
        }
        grid_bar(++gen, j, tid);

        // ---- phase B: LSTM1 GEMM + gates ----
        gemm_mma<2560, KST1>(dsm, j, tid,
                             g_h0h[wb], g_h0l[wb], 4,
                             g_cxh[rb], g_cxl[rb], 6,
                             g_h1h[rb], g_h1l[rb], g_pb1, zf);
        if (tid < 256) {
            float zi = l1b[du], zff = l1b[1024 + du];
            float zg = l1b[2048 + du], zo = l1b[3072 + du];
            #pragma unroll
            for (int s = 0; s < 8; s++) {
                const float* zp = zf + s * 1024 + bq * 32;
                zi += zp[dd]; zff += zp[8 + dd]; zg += zp[16 + dd]; zo += zp[24 + dd];
            }
            float ii = sigmoidf_(zi), ff = sigmoidf_(zff), oo = sigmoidf_(zo);
            c1r = ff * c1r + ii * tanhf(zg);
            float h = oo * tanhf(c1r);
            frag_store(g_h1h[wb], g_h1l[wb], bq, du >> 8, du & 255, h);
            __stcg(&g_h1[wb][bq * DDIM + du], h);
            __stcs(&g_h1all[((size_t)t * BN + bq) * DDIM + du], h);   // streaming
        }
        grid_bar(++gen, j, tid);

        // ---- phase C: attention energies (CTA = b x a-chunk) ----
        {
            const float* h1cur = g_h1[wb];
            for (int i = tid; i < DDIM; i += NTHR)
                sc->h1s[i] = __ldcg(h1cur + ab * DDIM + i);
            for (int i = tid; i < TIN + KSZ - 1; i += NTHR) {
                int jj = i - (KSZ / 2);
                sc->wp[i] = (jj >= 0 && jj < TIN) ? __ldcg(&g_wcum[ab * TIN + jj]) : 0.f;
            }
            for (int i = tid; i < KSZ * NFLT; i += NTHR) sc->cws[i] = cw[i];
            if (tid < NFLT) sc->cbs[tid] = cb[tid];
            for (int i = tid; i < NFLT * 32; i += NTHR)
                sc->ldws[i] = ldw[(i >> 5) * ADIM + ach * 32 + (i & 31)];
            if (tid < 32) {
                sc->ldbs[tid] = ldb[ach * 32 + tid];
                sc->vws[tid]  = vw[ach * 32 + tid];
            }
            __syncthreads();
            {   // qp partials: 32 parts x 32 k
                int al = tid & 31, part = tid >> 5;
                float a0 = 0.f;
                int k0 = part * 32;
                #pragma unroll 8
                for (int k = k0; k < k0 + 32; k++)
                    a0 += sc->h1s[k] * qw[k * ADIM + ach * 32 + al];
                sc->qred[part][al] = a0;
            }
            {   // conv: thread (ti, fq) does 8 filters
                int ti = tid & 255, fq = tid >> 8;
                float lf[8];
                #pragma unroll
                for (int f = 0; f < 8; f++) lf[f] = sc->cbs[fq * 8 + f];
                for (int jk = 0; jk < KSZ; jk++) {
                    float w = sc->wp[ti + jk];
                    #pragma unroll
                    for (int f = 0; f < 8; f++)
                        lf[f] += w * sc->cws[jk * NFLT + fq * 8 + f];
                }
                #pragma unroll
                for (int f = 0; f < 8; f++) sc->loc[ti][fq * 8 + f] = lf[f];
            }
            __syncthreads();
            if (tid < 32) {
                float s = 0.f;
                #pragma unroll
                for (int p = 0; p < 32; p++) s += sc->qred[p][tid];
                sc->qp[tid] = s + qb[ach * 32 + tid];
            }
            __syncthreads();
            {   // energies: thread (ti, ah) does 8 a's; keys direct from L2
                int ti = tid & 255, ah = tid >> 8;
                const float* kb = g_keysT + ((size_t)ab * ADIM + ach * 32) * TIN;
                float s[8];
                #pragma unroll
                for (int a8 = 0; a8 < 8; a8++) {
                    int al = ah * 8 + a8;
                    s[a8] = sc->qp[al] + __ldg(kb + al * TIN + ti) + sc->ldbs[al];
                }
                #pragma unroll 4
                for (int f = 0; f < NFLT; f++) {
                    float lf = sc->loc[ti][f];
                    #pragma unroll
                    for (int a8 = 0; a8 < 8; a8++)
                        s[a8] += lf * sc->ldws[f * 32 + ah * 8 + a8];
                }
                float e = 0.f;
                #pragma unroll
                for (int a8 = 0; a8 < 8; a8++) {
                    float u = __expf(-2.f * fabsf(s[a8]));
                    float th = __fdividef(1.f - u, 1.f + u);
                    e += copysignf(th, s[a8]) * sc->vws[ah * 8 + a8];
                }
                sc->es[ah][ti] = e;
            }
            __syncthreads();
            if (tid < 256)
                __stcg(&g_epart[(ach * BN + ab) * TIN + tid],
                       sc->es[0][tid] + sc->es[1][tid] + sc->es[2][tid] + sc->es[3][tid]);
        }
        grid_bar(++gen, j, tid);

        // ---- phase D: softmax (no max pass; energies bounded) + context ----
        {
            const int ec = ach;
            float ex = 0.f;
            if (tid < 256) {
                float ev = vb[0] + g_maskneg[ab * TIN + tid];
                #pragma unroll
                for (int ac = 0; ac < 4; ac++)
                    ev += __ldcg(&g_epart[(ac * BN + ab) * TIN + tid]);
                ex = expf(ev);
            }
            float s = ex;
            #pragma unroll
            for (int o = 16; o > 0; o >>= 1) s += __shfl_xor_sync(0xffffffffu, s, o);
            if (tid < 256 && (tid & 31) == 0) sd->red[tid >> 5] = s;
            __syncthreads();
            float tot = 0.f;
            #pragma unroll
            for (int i = 0; i < 8; i++) tot += sd->red[i];
            float inv = 1.f / tot;
            if (tid < 256) {
                float w = ex * inv;
                sd->ws[tid] = w;
                if (ec == 0) {
                    __stcg(&g_wcum[ab * TIN + tid],
                           __ldcg(&g_wcum[ab * TIN + tid]) + w);
                    __stcs(&out_align[((size_t)ab * TOUT + t) * TIN + tid], w);  // streaming
                }
            }
            __syncthreads();
            {   // context: 128 cols x 8 t-slices
                int cl = tid & 127, q = tid >> 7;
                float acc = 0.f;
                #pragma unroll 4
                for (int tt = q * 32; tt < q * 32 + 32; tt++)
                    acc += sd->ws[tt] *
                           __ldg(&memory[((size_t)ab * TIN + tt) * EDIM + ec * 128 + cl]);
                sd->cred[q][cl] = acc;
                __syncthreads();
                if (tid < 128) {
                    float cv = 0.f;
                    #pragma unroll
                    for (int q2 = 0; q2 < 8; q2++) cv += sd->cred[q2][tid];
                    int e = ec * 128 + tid;
                    frag_store(g_cxh[wb], g_cxl[wb], ab, e >> 8, e & 255, cv);
                    __stcs(&g_ctxall[((size_t)t * BN + ab) * EDIM + e], cv);     // streaming
                }
            }
        }
        grid_bar(++gen, j, tid);
    }
}

// ---------------- prenet: writes fragment buffers (+ mask in block 0) -------
__global__ void prenet_kernel(const float* __restrict__ targets,
                              const float* __restrict__ w1, const float* __restrict__ b1,
                              const float* __restrict__ w2, const float* __restrict__ b2,
                              const unsigned char* __restrict__ mask) {
    int bid = blockIdx.x;
    int t = bid >> 5, b = bid & 31;
    __shared__ float xin[NMEL];
    __shared__ float h[PRE];
    __shared__ int s_has;
    int tid = threadIdx.x;
    if (tid < NMEL) xin[tid] = (t == 0) ? 0.f : targets[(b * TOUT + (t - 1)) * NMEL + tid];
    __syncthreads();
    float acc = b1[tid];
    #pragma unroll 8
    for (int k = 0; k < NMEL; k++) acc += xin[k] * w1[k * PRE + tid];
    h[tid] = fmaxf(acc, 0.f);
    __syncthreads();
    float acc2 = b2[tid];
    #pragma unroll 8
    for (int k = 0; k < PRE; k++) acc2 += h[k] * w2[k * PRE + tid];
    frag_store(g_pnh + (size_t)t * 4096, g_pnl + (size_t)t * 4096,
               b, 0, tid, fmaxf(acc2, 0.f));

    if (bid == 0) {
        if (tid == 0) s_has = 0;
        __syncthreads();
        int local = 0;
        for (int i = tid; i < BN * TIN; i += 256)
            if ((i & 3) != 0 && mask[i] != 0) local = 1;
        if (local) atomicOr(&s_has, 1);
        __syncthreads();
        bool is_u8 = (s_has != 0);
        const int* mi = (const int*)mask;
        for (int i = tid; i < BN * TIN; i += 256) {
            int v = is_u8 ? (int)mask[i] : mi[i];
            g_maskneg[i] = v ? 0.f : -1e9f;
        }
    }
}

// ---------------- keys projection ----------------
__global__ void keys_kernel(const float* __restrict__ memory,
                            const float* __restrict__ mw, const float* __restrict__ mb) {
    int bid = blockIdx.x;
    int b = bid >> 8, t = bid & 255;
    __shared__ float x[EDIM];
    int tid = threadIdx.x;
    for (int i = tid; i < EDIM; i += 128) x[i] = memory[(b * TIN + t) * EDIM + i];
    __syncthreads();
    float acc = mb[tid];
    #pragma unroll 8
    for (int k = 0; k < EDIM; k++) acc += x[k] * mw[k * ADIM + tid];
    g_keysT[(b * ADIM + tid) * TIN + t] = acc;
}

// ---------------- output projections ----------------
__global__ void proj_kernel(const float* __restrict__ pw, const float* __restrict__ pb,
                            const float* __restrict__ gw, const float* __restrict__ gb,
                            float* __restrict__ out_mel, float* __restrict__ out_gate) {
    int bid = blockIdx.x;
    int t = bid >> 5, b = bid & 31;
    __shared__ float xo[DDIM + EDIM];
    int tid = threadIdx.x;
    for (int i = tid; i < DDIM; i += 128) xo[i] = __ldcs(&g_h1all[(size_t)(t * BN + b) * DDIM + i]);
    for (int i = tid; i < EDIM; i += 128) xo[DDIM + i] = __ldcs(&g_ctxall[(size_t)(t * BN + b) * EDIM + i]);
    __syncthreads();
    if (tid < NMEL) {
        float acc = pb[tid];
        #pragma unroll 8
        for (int k = 0; k < DDIM + EDIM; k++) acc += xo[k] * pw[k * NMEL + tid];
        out_mel[(size_t)(b * TOUT + t) * NMEL + tid] = acc;
    } else if (tid == NMEL) {
        float acc = gb[0];
        for (int k = 0; k < DDIM + EDIM; k++) acc += xo[k] * gw[k];
        out_gate[b * TOUT + t] = acc;
    }
}

// ---------------- launcher ----------------
extern "C" void kernel_launch(void* const* d_in, const int* in_sizes, int n_in,
                              void* d_out, int out_size) {
    (void)in_sizes; (void)n_in; (void)out_size;
    const float* memory  = (const float*)d_in[0];
    const float* targets = (const float*)d_in[1];
    const unsigned char* mask = (const unsigned char*)d_in[2];
    const float* p1w = (const float*)d_in[3];
    const float* p1b = (const float*)d_in[4];
    const float* p2w = (const float*)d_in[5];
    const float* p2b = (const float*)d_in[6];
    const float* l0k = (const float*)d_in[7];
    const float* l0r = (const float*)d_in[8];
    const float* l0b = (const float*)d_in[9];
    const float* l1k = (const float*)d_in[10];
    const float* l1r = (const float*)d_in[11];
    const float* l1b = (const float*)d_in[12];
    const float* qw  = (const float*)d_in[13];
    const float* qb  = (const float*)d_in[14];
    const float* mw  = (const float*)d_in[15];
    const float* mb  = (const float*)d_in[16];
    const float* vw  = (const float*)d_in[17];
    const float* vb  = (const float*)d_in[18];
    const float* ccw = (const float*)d_in[19];
    const float* ccb = (const float*)d_in[20];
    const float* ldw = (const float*)d_in[21];
    const float* ldb = (const float*)d_in[22];
    const float* pw  = (const float*)d_in[23];
    const float* pb  = (const float*)d_in[24];
    const float* gw  = (const float*)d_in[25];
    const float* gb  = (const float*)d_in[26];

    float* out       = (float*)d_out;
    float* out_mel   = out;
    float* out_gate  = out + (size_t)BN * TOUT * NMEL;
    float* out_align = out_gate + (size_t)BN * TOUT;

    static int smem_set = 0;
    if (!smem_set) {
        cudaFuncSetAttribute(decoder_persist,
                             cudaFuncAttributeMaxDynamicSharedMemorySize, DSMEM_BYTES);
        smem_set = 1;
    }

    uint4* pb0;
    uint4* pb1;
    cudaGetSymbolAddress((void**)&pb0, g_pb0);
    cudaGetSymbolAddress((void**)&pb1, g_pb1);

    pack_all_kernel<<<(KST0 + KST1) * 32, 256>>>(l0k, l0r, l1k, l1r, pb0, pb1);
    prenet_kernel<<<TOUT * BN, 256>>>(targets, p1w, p1b, p2w, p2b, mask);
    keys_kernel<<<BN * TIN, 128>>>(memory, mw, mb);
    decoder_persist<<<NCTA, NTHR, DSMEM_BYTES>>>(memory, l0b, l1b, qw, qb, vw, vb,
                                                 ccw, ccb, ldw, ldb, out_align);
    proj_kernel<<<TOUT * BN, 128>>>(pw, pb, gw, gb, out_mel, out_gate);
}